// round 14
// baseline (speedup 1.0000x reference)
#include <cuda_runtime.h>
#include <math.h>

#define HID 1024
#define LEN 40
#define VOC 50257
#define NPART 3142   // ceil(VOC/16) logits blocks

// front-kernel block roles
#define FR_COMB   64                  // blocks [0,64): comb (16 rows each)
#define FR_WHH1   (FR_COMB + 256)     // [64,320): whh1 partials
#define FR_LSTM0  (FR_WHH1 + 256)     // [320,576): lstm layer-0 cells
// back-kernel block roles
#define BK_LSTM1  256                 // [0,256): lstm layer-1 cells

// ---- scratch (no allocations allowed) ----
__device__ float g_concat[3 * HID];   // [embedded ; attn_applied]
__device__ float g_x[HID];            // relu(comb) output
__device__ float g_hl0[HID];          // layer-0 hidden out
__device__ float g_hl1[HID];          // layer-1 hidden out
__device__ float g_hh1[4 * HID];      // w_hh1·h0[1] partials (layer 1)
__device__ float g_pm[NPART];         // per-block logit max
__device__ float g_ps[NPART];         // per-block expsum
__device__ int   g_cflag[FR_COMB];    // comb block-done flags
__device__ int   g_hflag[BK_LSTM1];   // lstm1 block-done flags

#define GDC_LAUNCH() asm volatile("griddepcontrol.launch_dependents;")
#define GDC_WAIT()   asm volatile("griddepcontrol.wait;" ::: "memory")

__device__ __forceinline__ float warp_reduce(float s) {
#pragma unroll
    for (int o = 16; o; o >>= 1) s += __shfl_down_sync(0xFFFFFFFFu, s, o);
    return s;
}

__device__ __forceinline__ float dot4(float4 a, float4 b) {
    return a.x * b.x + a.y * b.y + a.z * b.z + a.w * b.w;
}

// Four consecutive streaming LDG.128 (stride 512 B) in one asm block.
__device__ __forceinline__ void ldg4x4(const float4* p,
                                       float4& a, float4& b, float4& c, float4& d) {
    asm volatile(
        "ld.global.cs.v4.f32 {%0,%1,%2,%3}, [%16];\n\t"
        "ld.global.cs.v4.f32 {%4,%5,%6,%7}, [%16+512];\n\t"
        "ld.global.cs.v4.f32 {%8,%9,%10,%11}, [%16+1024];\n\t"
        "ld.global.cs.v4.f32 {%12,%13,%14,%15}, [%16+1536];"
        : "=f"(a.x), "=f"(a.y), "=f"(a.z), "=f"(a.w),
          "=f"(b.x), "=f"(b.y), "=f"(b.z), "=f"(b.w),
          "=f"(c.x), "=f"(c.y), "=f"(c.z), "=f"(c.w),
          "=f"(d.x), "=f"(d.y), "=f"(d.z), "=f"(d.w)
        : "l"(p));
}

// TWO 1024-float rows dotted against the same vector; 16 LDG in flight.
__device__ __forceinline__ void row2_dot_1k(const float4* wA, const float4* wB,
                                            const float4* v4, int lane,
                                            float& outA, float& outB) {
    float4 a0,a1,a2,a3,a4,a5,a6,a7;
    float4 b0,b1,b2,b3,b4,b5,b6,b7;
    ldg4x4(wA + lane,       a0, a1, a2, a3);
    ldg4x4(wA + lane + 128, a4, a5, a6, a7);
    ldg4x4(wB + lane,       b0, b1, b2, b3);
    ldg4x4(wB + lane + 128, b4, b5, b6, b7);
    float sA = 0.f, sB = 0.f;
    float4 v;
    v = v4[lane];       sA += dot4(v, a0); sB += dot4(v, b0);
    v = v4[lane + 32];  sA += dot4(v, a1); sB += dot4(v, b1);
    v = v4[lane + 64];  sA += dot4(v, a2); sB += dot4(v, b2);
    v = v4[lane + 96];  sA += dot4(v, a3); sB += dot4(v, b3);
    v = v4[lane + 128]; sA += dot4(v, a4); sB += dot4(v, b4);
    v = v4[lane + 160]; sA += dot4(v, a5); sB += dot4(v, b5);
    v = v4[lane + 192]; sA += dot4(v, a6); sB += dot4(v, b6);
    v = v4[lane + 224]; sA += dot4(v, a7); sB += dot4(v, b7);
    outA += sA; outB += sB;
}

// ---------------------------------------------------------------------------
// K1: flag reset + embedding gather + attention (one block)
// ---------------------------------------------------------------------------
__global__ void __launch_bounds__(512)
k_attn(const int* __restrict__ tok,
       const float* __restrict__ h0,
       const float* __restrict__ emb,
       const float* __restrict__ attn_w,
       const float* __restrict__ attn_b,
       const float* __restrict__ enc,
       float* __restrict__ out_attnw) {
    GDC_LAUNCH();     // release successors at entry (they gate on this grid)
    int t = threadIdx.x;
    // reset intra-grid flags for this replay (consumers run after this grid)
    if (t < FR_COMB) g_cflag[t] = 0;
    if (t < BK_LSTM1) g_hflag[t] = 0;

    __shared__ float s_ain[3 * HID];
    __shared__ float s_log[LEN];
    __shared__ float s_w[LEN];
    int token = tok[0];
    for (int i = t; i < HID; i += 512) {
        s_ain[i]           = emb[(size_t)token * HID + i];
        s_ain[HID + i]     = h0[i];
        s_ain[2 * HID + i] = h0[HID + i];
    }
    __syncthreads();

    int warp = t >> 5, lane = t & 31;   // 16 warps
    for (int l = warp; l < LEN; l += 16) {
        const float4* w = (const float4*)(attn_w + (size_t)l * 3 * HID);
        const float4* a = (const float4*)s_ain;
        float s = 0.f;
#pragma unroll
        for (int c = 0; c < 3; c++) {
            float4 w0, w1, w2, w3, w4, w5, w6, w7;
            const float4* base = w + lane + 256 * c;
            ldg4x4(base,       w0, w1, w2, w3);
            ldg4x4(base + 128, w4, w5, w6, w7);
            int i0 = lane + 256 * c;
            s += dot4(a[i0],       w0) + dot4(a[i0 + 32],  w1)
               + dot4(a[i0 + 64],  w2) + dot4(a[i0 + 96],  w3)
               + dot4(a[i0 + 128], w4) + dot4(a[i0 + 160], w5)
               + dot4(a[i0 + 192], w6) + dot4(a[i0 + 224], w7);
        }
        s = warp_reduce(s);
        if (lane == 0) s_log[l] = s + attn_b[l];
    }
    __syncthreads();

    if (t == 0) {
        float m = s_log[0];
        for (int l = 1; l < LEN; l++) m = fmaxf(m, s_log[l]);
        float sum = 0.f;
        for (int l = 0; l < LEN; l++) { float e = expf(s_log[l] - m); s_w[l] = e; sum += e; }
        float inv = 1.f / sum;
        for (int l = 0; l < LEN; l++) { s_w[l] *= inv; out_attnw[l] = s_w[l]; }
    }
    __syncthreads();

    for (int j = t; j < 2 * HID; j += 512) {
        float s = 0.f;
#pragma unroll
        for (int l = 0; l < LEN; l++) s += s_w[l] * enc[l * 2 * HID + j];
        g_concat[HID + j] = s;
    }
    for (int i = t; i < HID; i += 512) g_concat[i] = s_ain[i];
}

// ---------------------------------------------------------------------------
// K2 "front": comb | whh1 partials | lstm0 cells, one grid (576 blocks x 256).
// comb -> lstm0 dependency handled by per-block flags (producers have lower
// blockIdx => resident first; no deadlock).
// ---------------------------------------------------------------------------
__global__ void __launch_bounds__(256, 2)
k_front(const float* __restrict__ h0,
        const float* __restrict__ c0,
        const float* __restrict__ comb_w,
        const float* __restrict__ comb_b,
        const float* __restrict__ w_ih0,
        const float* __restrict__ w_hh0,
        const float* __restrict__ w_hh1,
        const float* __restrict__ b_ih0,
        const float* __restrict__ b_hh0,
        float* __restrict__ h_out,
        float* __restrict__ c_out) {
    GDC_LAUNCH();                                 // release back grid at entry
    int bid = blockIdx.x;
    int t = threadIdx.x;
    int wid = t >> 5, lane = t & 31;

    if (bid < FR_COMB) {
        // ---- comb: 8 warps x 2 rows = 16 rows/block ----
        int r0 = (bid * 8 + wid) * 2;
        const float4* wA = (const float4*)(comb_w + (size_t)r0 * 3 * HID);
        const float4* wB = (const float4*)(comb_w + (size_t)(r0 + 1) * 3 * HID);
        // prefetch chunk 0 pre-wait
        float4 a0,a1,a2,a3,a4,a5,a6,a7, b0,b1,b2,b3,b4,b5,b6,b7;
        ldg4x4(wA + lane,       a0, a1, a2, a3);
        ldg4x4(wA + lane + 128, a4, a5, a6, a7);
        ldg4x4(wB + lane,       b0, b1, b2, b3);
        ldg4x4(wB + lane + 128, b4, b5, b6, b7);
        GDC_WAIT();                               // g_concat ready (attn done)

        const float4* v = (const float4*)g_concat;
        float sA = 0.f, sB = 0.f;
        float4 vv;
        vv = v[lane];       sA += dot4(vv, a0); sB += dot4(vv, b0);
        vv = v[lane + 32];  sA += dot4(vv, a1); sB += dot4(vv, b1);
        vv = v[lane + 64];  sA += dot4(vv, a2); sB += dot4(vv, b2);
        vv = v[lane + 96];  sA += dot4(vv, a3); sB += dot4(vv, b3);
        vv = v[lane + 128]; sA += dot4(vv, a4); sB += dot4(vv, b4);
        vv = v[lane + 160]; sA += dot4(vv, a5); sB += dot4(vv, b5);
        vv = v[lane + 192]; sA += dot4(vv, a6); sB += dot4(vv, b6);
        vv = v[lane + 224]; sA += dot4(vv, a7); sB += dot4(vv, b7);
#pragma unroll
        for (int c = 1; c < 3; c++)
            row2_dot_1k(wA + 256 * c, wB + 256 * c, v + 256 * c, lane, sA, sB);
        sA = warp_reduce(sA);
        sB = warp_reduce(sB);
        if (lane == 0) {
            g_x[r0]     = fmaxf(sA + comb_b[r0], 0.f);
            g_x[r0 + 1] = fmaxf(sB + comb_b[r0 + 1], 0.f);
        }
        __syncthreads();
        __threadfence();
        if (t == 0) *((volatile int*)&g_cflag[bid]) = 1;

    } else if (bid < FR_WHH1) {
        // ---- layer-1 w_hh partials: input-only, no wait ----
        int r0 = ((bid - FR_COMB) * 8 + wid) * 2;
        const float4* wA = (const float4*)(w_hh1 + (size_t)r0 * HID);
        const float4* wB = (const float4*)(w_hh1 + (size_t)(r0 + 1) * HID);
        const float4* h4 = (const float4*)(h0 + HID);
        float sA = 0.f, sB = 0.f;
        row2_dot_1k(wA, wB, h4, lane, sA, sB);
        sA = warp_reduce(sA);
        sB = warp_reduce(sB);
        if (lane == 0) { g_hh1[r0] = sA; g_hh1[r0 + 1] = sB; }

    } else {
        // ---- lstm layer 0: 4 units/block ----
        __shared__ float s_g[4][4];
        int gate = wid & 3;
        int upair = wid >> 2;
        int u0 = (bid - FR_WHH1) * 4 + upair * 2;
        int r0 = gate * HID + u0;

        // pre-wait: w_hh0·h0 (inputs only) + w_ih0 prefetch
        const float4* whA = (const float4*)(w_hh0 + (size_t)r0 * HID);
        const float4* whB = (const float4*)(w_hh0 + (size_t)(r0 + 1) * HID);
        const float4* h4  = (const float4*)h0;
        float sA = 0.f, sB = 0.f;
        row2_dot_1k(whA, whB, h4, lane, sA, sB);

        const float4* wiA = (const float4*)(w_ih0 + (size_t)r0 * HID);
        const float4* wiB = (const float4*)(w_ih0 + (size_t)(r0 + 1) * HID);
        float4 a0,a1,a2,a3,a4,a5,a6,a7, b0,b1,b2,b3,b4,b5,b6,b7;
        ldg4x4(wiA + lane,       a0, a1, a2, a3);
        ldg4x4(wiA + lane + 128, a4, a5, a6, a7);
        ldg4x4(wiB + lane,       b0, b1, b2, b3);
        ldg4x4(wiB + lane + 128, b4, b5, b6, b7);
        GDC_WAIT();                               // attn done (flags valid)

        // wait for all comb blocks (per-block flags, distinct addresses)
        if (t < FR_COMB) {
            volatile int* cf = g_cflag;
            while (cf[t] == 0) __nanosleep(64);
        }
        __syncthreads();
        __threadfence();

        const float4* x4 = (const float4*)g_x;
        float4 v;
        v = x4[lane];       sA += dot4(v, a0); sB += dot4(v, b0);
        v = x4[lane + 32];  sA += dot4(v, a1); sB += dot4(v, b1);
        v = x4[lane + 64];  sA += dot4(v, a2); sB += dot4(v, b2);
        v = x4[lane + 96];  sA += dot4(v, a3); sB += dot4(v, b3);
        v = x4[lane + 128]; sA += dot4(v, a4); sB += dot4(v, b4);
        v = x4[lane + 160]; sA += dot4(v, a5); sB += dot4(v, b5);
        v = x4[lane + 192]; sA += dot4(v, a6); sB += dot4(v, b6);
        v = x4[lane + 224]; sA += dot4(v, a7); sB += dot4(v, b7);
        sA = warp_reduce(sA);
        sB = warp_reduce(sB);
        if (lane == 0) {
            s_g[gate][upair * 2]     = sA + b_ih0[r0]     + b_hh0[r0];
            s_g[gate][upair * 2 + 1] = sB + b_ih0[r0 + 1] + b_hh0[r0 + 1];
        }
        __syncthreads();

        if (t < 4) {
            int u = (bid - FR_WHH1) * 4 + t;
            float gi = s_g[0][t], gf = s_g[1][t], gg = s_g[2][t], go = s_g[3][t];
            float si = 1.f / (1.f + expf(-gi));
            float sf = 1.f / (1.f + expf(-gf));
            float so = 1.f / (1.f + expf(-go));
            float c2 = sf * c0[u] + si * tanhf(gg);
            float h2 = so * tanhf(c2);
            c_out[u] = c2;
            h_out[u] = h2;
            g_hl0[u] = h2;
        }
    }
}

// ---------------------------------------------------------------------------
// K3 "back": lstm1 cells | logits, one grid (3398 blocks x 256).
// lstm1 -> logits dependency via per-block flags.
// ---------------------------------------------------------------------------
__global__ void __launch_bounds__(256, 2)
k_back(const float* __restrict__ h0,
       const float* __restrict__ c0,
       const float* __restrict__ w_ih1,
       const float* __restrict__ b_ih1,
       const float* __restrict__ b_hh1,
       const float* __restrict__ out_w,
       const float* __restrict__ out_b,
       float* __restrict__ logits,
       float* __restrict__ h_out,
       float* __restrict__ c_out) {
    GDC_LAUNCH();                                 // release finish at entry
    int bid = blockIdx.x;
    int t = threadIdx.x;
    int wid = t >> 5, lane = t & 31;

    if (bid < BK_LSTM1) {
        // ---- lstm layer 1: 4 units/block (w_hh1 part precomputed) ----
        __shared__ float s_g[4][4];
        int gate = wid & 3;
        int upair = wid >> 2;
        int u0 = bid * 4 + upair * 2;
        int r0 = gate * HID + u0;

        const float4* wiA = (const float4*)(w_ih1 + (size_t)r0 * HID);
        const float4* wiB = (const float4*)(w_ih1 + (size_t)(r0 + 1) * HID);
        float4 a0,a1,a2,a3,a4,a5,a6,a7, b0,b1,b2,b3,b4,b5,b6,b7;
        ldg4x4(wiA + lane,       a0, a1, a2, a3);
        ldg4x4(wiA + lane + 128, a4, a5, a6, a7);
        ldg4x4(wiB + lane,       b0, b1, b2, b3);
        ldg4x4(wiB + lane + 128, b4, b5, b6, b7);
        GDC_WAIT();                               // front grid done: g_hl0, g_hh1

        const float4* x4 = (const float4*)g_hl0;
        float sA = 0.f, sB = 0.f;
        float4 v;
        v = x4[lane];       sA += dot4(v, a0); sB += dot4(v, b0);
        v = x4[lane + 32];  sA += dot4(v, a1); sB += dot4(v, b1);
        v = x4[lane + 64];  sA += dot4(v, a2); sB += dot4(v, b2);
        v = x4[lane + 96];  sA += dot4(v, a3); sB += dot4(v, b3);
        v = x4[lane + 128]; sA += dot4(v, a4); sB += dot4(v, b4);
        v = x4[lane + 160]; sA += dot4(v, a5); sB += dot4(v, b5);
        v = x4[lane + 192]; sA += dot4(v, a6); sB += dot4(v, b6);
        v = x4[lane + 224]; sA += dot4(v, a7); sB += dot4(v, b7);
        sA = warp_reduce(sA);
        sB = warp_reduce(sB);
        if (lane == 0) {
            s_g[gate][upair * 2]     = sA + g_hh1[r0]     + b_ih1[r0]     + b_hh1[r0];
            s_g[gate][upair * 2 + 1] = sB + g_hh1[r0 + 1] + b_ih1[r0 + 1] + b_hh1[r0 + 1];
        }
        __syncthreads();

        if (t < 4) {
            int u = bid * 4 + t;
            float gi = s_g[0][t], gf = s_g[1][t], gg = s_g[2][t], go = s_g[3][t];
            float si = 1.f / (1.f + expf(-gi));
            float sf = 1.f / (1.f + expf(-gf));
            float so = 1.f / (1.f + expf(-go));
            float c2 = sf * c0[HID + u] + si * tanhf(gg);
            float h2 = so * tanhf(c2);
            c_out[u] = c2;
            h_out[u] = h2;
            g_hl1[u] = h2;
        }
        __syncthreads();
        __threadfence();
        if (t == 0) *((volatile int*)&g_hflag[bid]) = 1;

    } else {
        // ---- logits: 8 warps x 2 rows, pre-wait weight prefetch ----
        __shared__ float s_l[16];
        int pb = bid - BK_LSTM1;
        int r0 = pb * 16 + wid * 2;
        bool pair = (r0 + 1 < VOC);
        bool single = (!pair) && (r0 < VOC);

        float4 a0,a1,a2,a3,a4,a5,a6,a7, b0,b1,b2,b3,b4,b5,b6,b7;
        if (pair) {
            const float4* wA = (const float4*)(out_w + (size_t)r0 * HID);
            const float4* wB = (const float4*)(out_w + (size_t)(r0 + 1) * HID);
            ldg4x4(wA + lane,       a0, a1, a2, a3);
            ldg4x4(wA + lane + 128, a4, a5, a6, a7);
            ldg4x4(wB + lane,       b0, b1, b2, b3);
            ldg4x4(wB + lane + 128, b4, b5, b6, b7);
        } else if (single) {
            const float4* wA = (const float4*)(out_w + (size_t)r0 * HID);
            ldg4x4(wA + lane,       a0, a1, a2, a3);
            ldg4x4(wA + lane + 128, a4, a5, a6, a7);
        }
        GDC_WAIT();                               // front done (flags valid)

        // wait for all lstm1 blocks (per-block flags, distinct addresses)
        {
            volatile int* hf = g_hflag;
            while (hf[t] == 0) __nanosleep(64);   // t in [0,256) covers all
        }
        __syncthreads();
        __threadfence();

        const float4* h4 = (const float4*)g_hl1;
        if (pair) {
            float sA = 0.f, sB = 0.f;
            float4 v;
            v = h4[lane];       sA += dot4(v, a0); sB += dot4(v, b0);
            v = h4[lane + 32];  sA += dot4(v, a1); sB += dot4(v, b1);
            v = h4[lane + 64];  sA += dot4(v, a2); sB += dot4(v, b2);
            v = h4[lane + 96];  sA += dot4(v, a3); sB += dot4(v, b3);
            v = h4[lane + 128]; sA += dot4(v, a4); sB += dot4(v, b4);
            v = h4[lane + 160]; sA += dot4(v, a5); sB += dot4(v, b5);
            v = h4[lane + 192]; sA += dot4(v, a6); sB += dot4(v, b6);
            v = h4[lane + 224]; sA += dot4(v, a7); sB += dot4(v, b7);
            sA = warp_reduce(sA);
            sB = warp_reduce(sB);
            if (lane == 0) {
                float lgA = sA + out_b[r0];
                float lgB = sB + out_b[r0 + 1];
                logits[r0] = lgA;
                logits[r0 + 1] = lgB;
                s_l[wid * 2] = lgA;
                s_l[wid * 2 + 1] = lgB;
            }
        } else if (single) {
            float s = dot4(h4[lane],       a0) + dot4(h4[lane + 32],  a1)
                    + dot4(h4[lane + 64],  a2) + dot4(h4[lane + 96],  a3)
                    + dot4(h4[lane + 128], a4) + dot4(h4[lane + 160], a5)
                    + dot4(h4[lane + 192], a6) + dot4(h4[lane + 224], a7);
            s = warp_reduce(s);
            if (lane == 0) {
                float lg = s + out_b[r0];
                logits[r0] = lg;
                s_l[wid * 2] = lg;
                s_l[wid * 2 + 1] = -INFINITY;
            }
        } else if (lane == 0) {
            s_l[wid * 2] = -INFINITY;
            s_l[wid * 2 + 1] = -INFINITY;
        }
        __syncthreads();

        if (t == 0) {
            float m = s_l[0];
#pragma unroll
            for (int k = 1; k < 16; k++) m = fmaxf(m, s_l[k]);
            float sum = 0.f;
#pragma unroll
            for (int k = 0; k < 16; k++) sum += expf(s_l[k] - m);
            g_pm[pb] = m;
            g_ps[pb] = sum;
        }
    }
}

// ---------------------------------------------------------------------------
// K4: fused log-sum-exp + subtract.
// ---------------------------------------------------------------------------
__global__ void __launch_bounds__(256)
k_finish(float* __restrict__ logits) {
    GDC_WAIT();
    __shared__ float red[256];
    int t = threadIdx.x;
    float m = -INFINITY;
    for (int i = t; i < NPART; i += 256) m = fmaxf(m, g_pm[i]);
    red[t] = m;
    __syncthreads();
#pragma unroll
    for (int o = 128; o; o >>= 1) {
        if (t < o) red[t] = fmaxf(red[t], red[t + o]);
        __syncthreads();
    }
    m = red[0];
    __syncthreads();
    float s = 0.f;
    for (int i = t; i < NPART; i += 256) s += g_ps[i] * expf(g_pm[i] - m);
    red[t] = s;
    __syncthreads();
#pragma unroll
    for (int o = 128; o; o >>= 1) {
        if (t < o) red[t] += red[t + o];
        __syncthreads();
    }
    __syncthreads();
    float lse = m + logf(red[0]);

    int idx = blockIdx.x * 256 + t;
    if (idx < VOC) logits[idx] -= lse;
}

// ---------------------------------------------------------------------------
// host: PDL launch helper
// ---------------------------------------------------------------------------
static void launch_pdl(const void* fn, dim3 grid, dim3 block, void** args) {
    cudaLaunchConfig_t cfg = {};
    cfg.gridDim = grid;
    cfg.blockDim = block;
    cfg.dynamicSmemBytes = 0;
    cfg.stream = 0;
    cudaLaunchAttribute at[1];
    at[0].id = cudaLaunchAttributeProgrammaticStreamSerialization;
    at[0].val.programmaticStreamSerializationAllowed = 1;
    cfg.attrs = at;
    cfg.numAttrs = 1;
    cudaLaunchKernelExC(&cfg, fn, args);
}

// ---------------------------------------------------------------------------
// Output layout: [log_probs(V) | h_new(2*H) | c_new(2*H) | attn_weights(L)]
// ---------------------------------------------------------------------------
extern "C" void kernel_launch(void* const* d_in, const int* in_sizes, int n_in,
                              void* d_out, int out_size) {
    const int*   tok    = (const int*)  d_in[0];
    const float* h0     = (const float*)d_in[1];
    const float* c0     = (const float*)d_in[2];
    const float* enc    = (const float*)d_in[3];
    const float* emb    = (const float*)d_in[4];
    const float* attn_w = (const float*)d_in[5];
    const float* attn_b = (const float*)d_in[6];
    const float* comb_w = (const float*)d_in[7];
    const float* comb_b = (const float*)d_in[8];
    const float* w_ih0  = (const float*)d_in[9];
    const float* w_hh0  = (const float*)d_in[10];
    const float* b_ih0  = (const float*)d_in[11];
    const float* b_hh0  = (const float*)d_in[12];
    const float* w_ih1  = (const float*)d_in[13];
    const float* w_hh1  = (const float*)d_in[14];
    const float* b_ih1  = (const float*)d_in[15];
    const float* b_hh1  = (const float*)d_in[16];
    const float* out_w  = (const float*)d_in[17];
    const float* out_b  = (const float*)d_in[18];

    float* out      = (float*)d_out;
    float* o_logp   = out;
    float* o_h      = out + VOC;
    float* o_c      = out + VOC + 2 * HID;
    float* o_attn   = out + VOC + 4 * HID;

    k_attn<<<1, 512>>>(tok, h0, emb, attn_w, attn_b, enc, o_attn);

    {
        float* ho = o_h;
        float* co = o_c;
        void* args[] = {(void*)&h0, (void*)&c0, (void*)&comb_w, (void*)&comb_b,
                        (void*)&w_ih0, (void*)&w_hh0, (void*)&w_hh1,
                        (void*)&b_ih0, (void*)&b_hh0, &ho, &co};
        launch_pdl((const void*)k_front, dim3(FR_LSTM0), dim3(256), args);
    }
    {
        float* ho = o_h + HID;
        float* co = o_c + HID;
        void* args[] = {(void*)&h0, (void*)&c0, (void*)&w_ih1,
                        (void*)&b_ih1, (void*)&b_hh1,
                        (void*)&out_w, (void*)&out_b,
                        (void*)&o_logp, &ho, &co};
        launch_pdl((const void*)k_back, dim3(BK_LSTM1 + NPART), dim3(256), args);
    }
    {
        void* args[] = {(void*)&o_logp};
        launch_pdl((const void*)k_finish, dim3((VOC + 255) / 256), dim3(256), args);
    }
}

// round 15
// speedup vs baseline: 1.0786x; 1.0786x over previous
#include <cuda_runtime.h>
#include <math.h>

#define HID 1024
#define LEN 40
#define VOC 50257
#define NPART 3142   // ceil(VOC/16) logits blocks
#define BK_LSTM1 256 // back-grid blocks [0,256): lstm layer-1 cells

// ---- scratch (no allocations allowed) ----
__device__ float g_concat[3 * HID];   // [embedded ; attn_applied]
__device__ float g_x[HID];            // relu(comb) output
__device__ float g_hl0[HID];          // layer-0 hidden out
__device__ float g_hl1[HID];          // layer-1 hidden out
__device__ float g_hh1[4 * HID];      // w_hh1·h0[1] partials (layer 1)
__device__ float g_pm[NPART];         // per-block logit max
__device__ float g_ps[NPART];         // per-block expsum
__device__ int   g_hcnt;              // lstm1 completion counter

#define GDC_LAUNCH() asm volatile("griddepcontrol.launch_dependents;")
#define GDC_WAIT()   asm volatile("griddepcontrol.wait;" ::: "memory")

__device__ __forceinline__ float warp_reduce(float s) {
#pragma unroll
    for (int o = 16; o; o >>= 1) s += __shfl_down_sync(0xFFFFFFFFu, s, o);
    return s;
}

__device__ __forceinline__ float dot4(float4 a, float4 b) {
    return a.x * b.x + a.y * b.y + a.z * b.z + a.w * b.w;
}

// Four consecutive streaming LDG.128 (stride 512 B) in one asm block.
__device__ __forceinline__ void ldg4x4(const float4* p,
                                       float4& a, float4& b, float4& c, float4& d) {
    asm volatile(
        "ld.global.cs.v4.f32 {%0,%1,%2,%3}, [%16];\n\t"
        "ld.global.cs.v4.f32 {%4,%5,%6,%7}, [%16+512];\n\t"
        "ld.global.cs.v4.f32 {%8,%9,%10,%11}, [%16+1024];\n\t"
        "ld.global.cs.v4.f32 {%12,%13,%14,%15}, [%16+1536];"
        : "=f"(a.x), "=f"(a.y), "=f"(a.z), "=f"(a.w),
          "=f"(b.x), "=f"(b.y), "=f"(b.z), "=f"(b.w),
          "=f"(c.x), "=f"(c.y), "=f"(c.z), "=f"(c.w),
          "=f"(d.x), "=f"(d.y), "=f"(d.z), "=f"(d.w)
        : "l"(p));
}

// TWO 1024-float rows dotted against the same vector; 16 LDG in flight.
__device__ __forceinline__ void row2_dot_1k(const float4* wA, const float4* wB,
                                            const float4* v4, int lane,
                                            float& outA, float& outB) {
    float4 a0,a1,a2,a3,a4,a5,a6,a7;
    float4 b0,b1,b2,b3,b4,b5,b6,b7;
    ldg4x4(wA + lane,       a0, a1, a2, a3);
    ldg4x4(wA + lane + 128, a4, a5, a6, a7);
    ldg4x4(wB + lane,       b0, b1, b2, b3);
    ldg4x4(wB + lane + 128, b4, b5, b6, b7);
    float sA = 0.f, sB = 0.f;
    float4 v;
    v = v4[lane];       sA += dot4(v, a0); sB += dot4(v, b0);
    v = v4[lane + 32];  sA += dot4(v, a1); sB += dot4(v, b1);
    v = v4[lane + 64];  sA += dot4(v, a2); sB += dot4(v, b2);
    v = v4[lane + 96];  sA += dot4(v, a3); sB += dot4(v, b3);
    v = v4[lane + 128]; sA += dot4(v, a4); sB += dot4(v, b4);
    v = v4[lane + 160]; sA += dot4(v, a5); sB += dot4(v, b5);
    v = v4[lane + 192]; sA += dot4(v, a6); sB += dot4(v, b6);
    v = v4[lane + 224]; sA += dot4(v, a7); sB += dot4(v, b7);
    outA += sA; outB += sB;
}

// ---------------------------------------------------------------------------
// K1: counter reset + embedding gather + attention (one block)
// ---------------------------------------------------------------------------
__global__ void __launch_bounds__(512)
k_attn(const int* __restrict__ tok,
       const float* __restrict__ h0,
       const float* __restrict__ emb,
       const float* __restrict__ attn_w,
       const float* __restrict__ attn_b,
       const float* __restrict__ enc,
       float* __restrict__ out_attnw) {
    GDC_LAUNCH();     // release successors at entry
    int t = threadIdx.x;
    if (t == 0) g_hcnt = 0;            // reset for this replay (ordered by GDC chain)

    __shared__ float s_ain[3 * HID];
    __shared__ float s_log[LEN];
    __shared__ float s_w[LEN];
    int token = tok[0];
    for (int i = t; i < HID; i += 512) {
        s_ain[i]           = emb[(size_t)token * HID + i];
        s_ain[HID + i]     = h0[i];
        s_ain[2 * HID + i] = h0[HID + i];
    }
    __syncthreads();

    int warp = t >> 5, lane = t & 31;   // 16 warps
    for (int l = warp; l < LEN; l += 16) {
        const float4* w = (const float4*)(attn_w + (size_t)l * 3 * HID);
        const float4* a = (const float4*)s_ain;
        float s = 0.f;
#pragma unroll
        for (int c = 0; c < 3; c++) {
            float4 w0, w1, w2, w3, w4, w5, w6, w7;
            const float4* base = w + lane + 256 * c;
            ldg4x4(base,       w0, w1, w2, w3);
            ldg4x4(base + 128, w4, w5, w6, w7);
            int i0 = lane + 256 * c;
            s += dot4(a[i0],       w0) + dot4(a[i0 + 32],  w1)
               + dot4(a[i0 + 64],  w2) + dot4(a[i0 + 96],  w3)
               + dot4(a[i0 + 128], w4) + dot4(a[i0 + 160], w5)
               + dot4(a[i0 + 192], w6) + dot4(a[i0 + 224], w7);
        }
        s = warp_reduce(s);
        if (lane == 0) s_log[l] = s + attn_b[l];
    }
    __syncthreads();

    if (t == 0) {
        float m = s_log[0];
        for (int l = 1; l < LEN; l++) m = fmaxf(m, s_log[l]);
        float sum = 0.f;
        for (int l = 0; l < LEN; l++) { float e = expf(s_log[l] - m); s_w[l] = e; sum += e; }
        float inv = 1.f / sum;
        for (int l = 0; l < LEN; l++) { s_w[l] *= inv; out_attnw[l] = s_w[l]; }
    }
    __syncthreads();

    for (int j = t; j < 2 * HID; j += 512) {
        float s = 0.f;
#pragma unroll
        for (int l = 0; l < LEN; l++) s += s_w[l] * enc[l * 2 * HID + j];
        g_concat[HID + j] = s;
    }
    for (int i = t; i < HID; i += 512) g_concat[i] = s_ain[i];
}

// ---------------------------------------------------------------------------
// K2: x = relu([emb;attn] @ comb_w.T + comb_b). Warp per ROW-PAIR.
// ---------------------------------------------------------------------------
__global__ void __launch_bounds__(128, 2)
k_comb(const float* __restrict__ comb_w,
       const float* __restrict__ comb_b) {
    GDC_LAUNCH();
    int t = threadIdx.x;
    int wid = t >> 5, lane = t & 31;
    int r0 = (blockIdx.x * 4 + wid) * 2;          // even row of pair
    const float4* wA = (const float4*)(comb_w + (size_t)r0 * 3 * HID);
    const float4* wB = (const float4*)(comb_w + (size_t)(r0 + 1) * 3 * HID);

    // prefetch chunk 0 (independent of parent)
    float4 a0,a1,a2,a3,a4,a5,a6,a7, b0,b1,b2,b3,b4,b5,b6,b7;
    ldg4x4(wA + lane,       a0, a1, a2, a3);
    ldg4x4(wA + lane + 128, a4, a5, a6, a7);
    ldg4x4(wB + lane,       b0, b1, b2, b3);
    ldg4x4(wB + lane + 128, b4, b5, b6, b7);
    GDC_WAIT();                                   // g_concat ready

    const float4* v = (const float4*)g_concat;
    float sA = 0.f, sB = 0.f;
    float4 vv;
    vv = v[lane];       sA += dot4(vv, a0); sB += dot4(vv, b0);
    vv = v[lane + 32];  sA += dot4(vv, a1); sB += dot4(vv, b1);
    vv = v[lane + 64];  sA += dot4(vv, a2); sB += dot4(vv, b2);
    vv = v[lane + 96];  sA += dot4(vv, a3); sB += dot4(vv, b3);
    vv = v[lane + 128]; sA += dot4(vv, a4); sB += dot4(vv, b4);
    vv = v[lane + 160]; sA += dot4(vv, a5); sB += dot4(vv, b5);
    vv = v[lane + 192]; sA += dot4(vv, a6); sB += dot4(vv, b6);
    vv = v[lane + 224]; sA += dot4(vv, a7); sB += dot4(vv, b7);
#pragma unroll
    for (int c = 1; c < 3; c++)
        row2_dot_1k(wA + 256 * c, wB + 256 * c, v + 256 * c, lane, sA, sB);
    sA = warp_reduce(sA);
    sB = warp_reduce(sB);
    if (lane == 0) {
        g_x[r0]     = fmaxf(sA + comb_b[r0], 0.f);
        g_x[r0 + 1] = fmaxf(sB + comb_b[r0 + 1], 0.f);
    }
}

// ---------------------------------------------------------------------------
// K3a: blocks [0,256): layer-1 w_hh partials (INPUT-ONLY, no wait).
//      blocks [256,512): full lstm layer-0 cell with PDL.
// ---------------------------------------------------------------------------
__global__ void __launch_bounds__(256, 2)
k_lstm_a(const float* __restrict__ h0,
         const float* __restrict__ c0,
         const float* __restrict__ w_ih0,
         const float* __restrict__ w_hh0,
         const float* __restrict__ w_hh1,
         const float* __restrict__ b_ih0,
         const float* __restrict__ b_hh0,
         float* __restrict__ h_out,
         float* __restrict__ c_out) {
    GDC_LAUNCH();
    int bid = blockIdx.x;
    int t = threadIdx.x;
    int wid = t >> 5, lane = t & 31;

    if (bid < 256) {
        // ---- layer-1 w_hh partials: 4096 rows, 2 rows/warp ----
        int r0 = (bid * 8 + wid) * 2;
        const float4* wA = (const float4*)(w_hh1 + (size_t)r0 * HID);
        const float4* wB = (const float4*)(w_hh1 + (size_t)(r0 + 1) * HID);
        const float4* h4 = (const float4*)(h0 + HID);
        float sA = 0.f, sB = 0.f;
        row2_dot_1k(wA, wB, h4, lane, sA, sB);
        sA = warp_reduce(sA);
        sB = warp_reduce(sB);
        if (lane == 0) { g_hh1[r0] = sA; g_hh1[r0 + 1] = sB; }
        return;
    }

    // ---- lstm layer 0: 4 units/block ----
    __shared__ float s_g[4][4];
    int gate = wid & 3;
    int upair = wid >> 2;
    int u0 = (bid - 256) * 4 + upair * 2;
    int r0 = gate * HID + u0;

    // pre-wait: w_hh0·h0 (inputs only) + w_ih0 prefetch
    const float4* whA = (const float4*)(w_hh0 + (size_t)r0 * HID);
    const float4* whB = (const float4*)(w_hh0 + (size_t)(r0 + 1) * HID);
    const float4* h4  = (const float4*)h0;
    float sA = 0.f, sB = 0.f;
    row2_dot_1k(whA, whB, h4, lane, sA, sB);

    const float4* wiA = (const float4*)(w_ih0 + (size_t)r0 * HID);
    const float4* wiB = (const float4*)(w_ih0 + (size_t)(r0 + 1) * HID);
    float4 a0,a1,a2,a3,a4,a5,a6,a7, b0,b1,b2,b3,b4,b5,b6,b7;
    ldg4x4(wiA + lane,       a0, a1, a2, a3);
    ldg4x4(wiA + lane + 128, a4, a5, a6, a7);
    ldg4x4(wiB + lane,       b0, b1, b2, b3);
    ldg4x4(wiB + lane + 128, b4, b5, b6, b7);
    GDC_WAIT();                                   // g_x ready

    const float4* x4 = (const float4*)g_x;
    float4 v;
    v = x4[lane];       sA += dot4(v, a0); sB += dot4(v, b0);
    v = x4[lane + 32];  sA += dot4(v, a1); sB += dot4(v, b1);
    v = x4[lane + 64];  sA += dot4(v, a2); sB += dot4(v, b2);
    v = x4[lane + 96];  sA += dot4(v, a3); sB += dot4(v, b3);
    v = x4[lane + 128]; sA += dot4(v, a4); sB += dot4(v, b4);
    v = x4[lane + 160]; sA += dot4(v, a5); sB += dot4(v, b5);
    v = x4[lane + 192]; sA += dot4(v, a6); sB += dot4(v, b6);
    v = x4[lane + 224]; sA += dot4(v, a7); sB += dot4(v, b7);
    sA = warp_reduce(sA);
    sB = warp_reduce(sB);
    if (lane == 0) {
        s_g[gate][upair * 2]     = sA + b_ih0[r0]     + b_hh0[r0];
        s_g[gate][upair * 2 + 1] = sB + b_ih0[r0 + 1] + b_hh0[r0 + 1];
    }
    __syncthreads();

    if (t < 4) {
        int u = (bid - 256) * 4 + t;
        float gi = s_g[0][t], gf = s_g[1][t], gg = s_g[2][t], go = s_g[3][t];
        float si = 1.f / (1.f + expf(-gi));
        float sf = 1.f / (1.f + expf(-gf));
        float so = 1.f / (1.f + expf(-go));
        float c2 = sf * c0[u] + si * tanhf(gg);
        float h2 = so * tanhf(c2);
        c_out[u] = c2;
        h_out[u] = h2;
        g_hl0[u] = h2;
    }
}

// ---------------------------------------------------------------------------
// K4 "back": lstm1 cells | logits in one grid. lstm1 -> logits sync via ONE
// counter, bumped once per lstm1 block, polled by ONE thread per logits block.
// ---------------------------------------------------------------------------
__global__ void __launch_bounds__(256, 2)
k_back(const float* __restrict__ h0,
       const float* __restrict__ c0,
       const float* __restrict__ w_ih1,
       const float* __restrict__ b_ih1,
       const float* __restrict__ b_hh1,
       const float* __restrict__ out_w,
       const float* __restrict__ out_b,
       float* __restrict__ logits,
       float* __restrict__ h_out,
       float* __restrict__ c_out) {
    GDC_LAUNCH();                                 // release finish at entry
    int bid = blockIdx.x;
    int t = threadIdx.x;
    int wid = t >> 5, lane = t & 31;

    if (bid < BK_LSTM1) {
        // ---- lstm layer 1: 4 units/block (w_hh1 part precomputed) ----
        __shared__ float s_g[4][4];
        int gate = wid & 3;
        int upair = wid >> 2;
        int u0 = bid * 4 + upair * 2;
        int r0 = gate * HID + u0;

        const float4* wiA = (const float4*)(w_ih1 + (size_t)r0 * HID);
        const float4* wiB = (const float4*)(w_ih1 + (size_t)(r0 + 1) * HID);
        float4 a0,a1,a2,a3,a4,a5,a6,a7, b0,b1,b2,b3,b4,b5,b6,b7;
        ldg4x4(wiA + lane,       a0, a1, a2, a3);
        ldg4x4(wiA + lane + 128, a4, a5, a6, a7);
        ldg4x4(wiB + lane,       b0, b1, b2, b3);
        ldg4x4(wiB + lane + 128, b4, b5, b6, b7);
        GDC_WAIT();                               // lstm_a done: g_hl0, g_hh1

        const float4* x4 = (const float4*)g_hl0;
        float sA = 0.f, sB = 0.f;
        float4 v;
        v = x4[lane];       sA += dot4(v, a0); sB += dot4(v, b0);
        v = x4[lane + 32];  sA += dot4(v, a1); sB += dot4(v, b1);
        v = x4[lane + 64];  sA += dot4(v, a2); sB += dot4(v, b2);
        v = x4[lane + 96];  sA += dot4(v, a3); sB += dot4(v, b3);
        v = x4[lane + 128]; sA += dot4(v, a4); sB += dot4(v, b4);
        v = x4[lane + 160]; sA += dot4(v, a5); sB += dot4(v, b5);
        v = x4[lane + 192]; sA += dot4(v, a6); sB += dot4(v, b6);
        v = x4[lane + 224]; sA += dot4(v, a7); sB += dot4(v, b7);
        sA = warp_reduce(sA);
        sB = warp_reduce(sB);
        if (lane == 0) {
            s_g[gate][upair * 2]     = sA + g_hh1[r0]     + b_ih1[r0]     + b_hh1[r0];
            s_g[gate][upair * 2 + 1] = sB + g_hh1[r0 + 1] + b_ih1[r0 + 1] + b_hh1[r0 + 1];
        }
        __syncthreads();

        if (t < 4) {
            int u = bid * 4 + t;
            float gi = s_g[0][t], gf = s_g[1][t], gg = s_g[2][t], go = s_g[3][t];
            float si = 1.f / (1.f + expf(-gi));
            float sf = 1.f / (1.f + expf(-gf));
            float so = 1.f / (1.f + expf(-go));
            float c2 = sf * c0[HID + u] + si * tanhf(gg);
            float h2 = so * tanhf(c2);
            c_out[u] = c2;
            h_out[u] = h2;
            g_hl1[u] = h2;
        }
        __syncthreads();
        __threadfence();
        if (t == 0) atomicAdd(&g_hcnt, 1);        // one atomic per block

    } else {
        // ---- logits: 8 warps x 2 rows, pre-wait weight prefetch ----
        __shared__ float s_l[16];
        int pb = bid - BK_LSTM1;
        int r0 = pb * 16 + wid * 2;
        bool pair = (r0 + 1 < VOC);
        bool single = (!pair) && (r0 < VOC);

        float4 a0,a1,a2,a3,a4,a5,a6,a7, b0,b1,b2,b3,b4,b5,b6,b7;
        if (pair) {
            const float4* wA = (const float4*)(out_w + (size_t)r0 * HID);
            const float4* wB = (const float4*)(out_w + (size_t)(r0 + 1) * HID);
            ldg4x4(wA + lane,       a0, a1, a2, a3);
            ldg4x4(wA + lane + 128, a4, a5, a6, a7);
            ldg4x4(wB + lane,       b0, b1, b2, b3);
            ldg4x4(wB + lane + 128, b4, b5, b6, b7);
        } else if (single) {
            const float4* wA = (const float4*)(out_w + (size_t)r0 * HID);
            ldg4x4(wA + lane,       a0, a1, a2, a3);
            ldg4x4(wA + lane + 128, a4, a5, a6, a7);
        }
        GDC_WAIT();                               // lstm_a done (counter valid)

        // ONE thread polls ONE counter with backoff — negligible L2 traffic
        if (t == 0) {
            volatile int* hc = &g_hcnt;
            while (*hc < BK_LSTM1) __nanosleep(200);
        }
        __syncthreads();
        __threadfence();

        const float4* h4 = (const float4*)g_hl1;
        if (pair) {
            float sA = 0.f, sB = 0.f;
            float4 v;
            v = h4[lane];       sA += dot4(v, a0); sB += dot4(v, b0);
            v = h4[lane + 32];  sA += dot4(v, a1); sB += dot4(v, b1);
            v = h4[lane + 64];  sA += dot4(v, a2); sB += dot4(v, b2);
            v = h4[lane + 96];  sA += dot4(v, a3); sB += dot4(v, b3);
            v = h4[lane + 128]; sA += dot4(v, a4); sB += dot4(v, b4);
            v = h4[lane + 160]; sA += dot4(v, a5); sB += dot4(v, b5);
            v = h4[lane + 192]; sA += dot4(v, a6); sB += dot4(v, b6);
            v = h4[lane + 224]; sA += dot4(v, a7); sB += dot4(v, b7);
            sA = warp_reduce(sA);
            sB = warp_reduce(sB);
            if (lane == 0) {
                float lgA = sA + out_b[r0];
                float lgB = sB + out_b[r0 + 1];
                logits[r0] = lgA;
                logits[r0 + 1] = lgB;
                s_l[wid * 2] = lgA;
                s_l[wid * 2 + 1] = lgB;
            }
        } else if (single) {
            float s = dot4(h4[lane],       a0) + dot4(h4[lane + 32],  a1)
                    + dot4(h4[lane + 64],  a2) + dot4(h4[lane + 96],  a3)
                    + dot4(h4[lane + 128], a4) + dot4(h4[lane + 160], a5)
                    + dot4(h4[lane + 192], a6) + dot4(h4[lane + 224], a7);
            s = warp_reduce(s);
            if (lane == 0) {
                float lg = s + out_b[r0];
                logits[r0] = lg;
                s_l[wid * 2] = lg;
                s_l[wid * 2 + 1] = -INFINITY;
            }
        } else if (lane == 0) {
            s_l[wid * 2] = -INFINITY;
            s_l[wid * 2 + 1] = -INFINITY;
        }
        __syncthreads();

        if (t == 0) {
            float m = s_l[0];
#pragma unroll
            for (int k = 1; k < 16; k++) m = fmaxf(m, s_l[k]);
            float sum = 0.f;
#pragma unroll
            for (int k = 0; k < 16; k++) sum += expf(s_l[k] - m);
            g_pm[pb] = m;
            g_ps[pb] = sum;
        }
    }
}

// ---------------------------------------------------------------------------
// K5: fused log-sum-exp + subtract.
// ---------------------------------------------------------------------------
__global__ void __launch_bounds__(256)
k_finish(float* __restrict__ logits) {
    GDC_WAIT();
    __shared__ float red[256];
    int t = threadIdx.x;
    float m = -INFINITY;
    for (int i = t; i < NPART; i += 256) m = fmaxf(m, g_pm[i]);
    red[t] = m;
    __syncthreads();
#pragma unroll
    for (int o = 128; o; o >>= 1) {
        if (t < o) red[t] = fmaxf(red[t], red[t + o]);
        __syncthreads();
    }
    m = red[0];
    __syncthreads();
    float s = 0.f;
    for (int i = t; i < NPART; i += 256) s += g_ps[i] * expf(g_pm[i] - m);
    red[t] = s;
    __syncthreads();
#pragma unroll
    for (int o = 128; o; o >>= 1) {
        if (t < o) red[t] += red[t + o];
        __syncthreads();
    }
    __syncthreads();
    float lse = m + logf(red[0]);

    int idx = blockIdx.x * 256 + t;
    if (idx < VOC) logits[idx] -= lse;
}

// ---------------------------------------------------------------------------
// host: PDL launch helper
// ---------------------------------------------------------------------------
static void launch_pdl(const void* fn, dim3 grid, dim3 block, void** args) {
    cudaLaunchConfig_t cfg = {};
    cfg.gridDim = grid;
    cfg.blockDim = block;
    cfg.dynamicSmemBytes = 0;
    cfg.stream = 0;
    cudaLaunchAttribute at[1];
    at[0].id = cudaLaunchAttributeProgrammaticStreamSerialization;
    at[0].val.programmaticStreamSerializationAllowed = 1;
    cfg.attrs = at;
    cfg.numAttrs = 1;
    cudaLaunchKernelExC(&cfg, fn, args);
}

// ---------------------------------------------------------------------------
// Output layout: [log_probs(V) | h_new(2*H) | c_new(2*H) | attn_weights(L)]
// ---------------------------------------------------------------------------
extern "C" void kernel_launch(void* const* d_in, const int* in_sizes, int n_in,
                              void* d_out, int out_size) {
    const int*   tok    = (const int*)  d_in[0];
    const float* h0     = (const float*)d_in[1];
    const float* c0     = (const float*)d_in[2];
    const float* enc    = (const float*)d_in[3];
    const float* emb    = (const float*)d_in[4];
    const float* attn_w = (const float*)d_in[5];
    const float* attn_b = (const float*)d_in[6];
    const float* comb_w = (const float*)d_in[7];
    const float* comb_b = (const float*)d_in[8];
    const float* w_ih0  = (const float*)d_in[9];
    const float* w_hh0  = (const float*)d_in[10];
    const float* b_ih0  = (const float*)d_in[11];
    const float* b_hh0  = (const float*)d_in[12];
    const float* w_ih1  = (const float*)d_in[13];
    const float* w_hh1  = (const float*)d_in[14];
    const float* b_ih1  = (const float*)d_in[15];
    const float* b_hh1  = (const float*)d_in[16];
    const float* out_w  = (const float*)d_in[17];
    const float* out_b  = (const float*)d_in[18];

    float* out      = (float*)d_out;
    float* o_logp   = out;
    float* o_h      = out + VOC;
    float* o_c      = out + VOC + 2 * HID;
    float* o_attn   = out + VOC + 4 * HID;

    k_attn<<<1, 512>>>(tok, h0, emb, attn_w, attn_b, enc, o_attn);

    {
        void* args[] = {(void*)&comb_w, (void*)&comb_b};
        launch_pdl((const void*)k_comb, dim3(128), dim3(128), args);
    }
    {
        float* ho = o_h;
        float* co = o_c;
        void* args[] = {(void*)&h0, (void*)&c0, (void*)&w_ih0, (void*)&w_hh0,
                        (void*)&w_hh1, (void*)&b_ih0, (void*)&b_hh0, &ho, &co};
        launch_pdl((const void*)k_lstm_a, dim3(512), dim3(256), args);
    }
    {
        float* ho = o_h + HID;
        float* co = o_c + HID;
        void* args[] = {(void*)&h0, (void*)&c0, (void*)&w_ih1,
                        (void*)&b_ih1, (void*)&b_hh1,
                        (void*)&out_w, (void*)&out_b,
                        (void*)&o_logp, &ho, &co};
        launch_pdl((const void*)k_back, dim3(BK_LSTM1 + NPART), dim3(256), args);
    }
    {
        void* args[] = {(void*)&o_logp};
        launch_pdl((const void*)k_finish, dim3((VOC + 255) / 256), dim3(256), args);
    }
}

// round 16
// speedup vs baseline: 1.1235x; 1.0416x over previous
#include <cuda_runtime.h>
#include <math.h>

#define HID 1024
#define LEN 40
#define VOC 50257
#define NPART 3142   // ceil(VOC/16) logits blocks

// ---- scratch (no allocations allowed) ----
__device__ float g_concat[3 * HID];   // [embedded ; attn_applied]
__device__ float g_x[HID];            // relu(comb) output
__device__ float g_hl0[HID];          // layer-0 hidden out
__device__ float g_hl1[HID];          // layer-1 hidden out
__device__ float g_hh1[4 * HID];      // w_hh1·h0[1] partials (layer 1)
__device__ float g_pm[NPART];         // per-block logit max
__device__ float g_ps[NPART];         // per-block expsum

#define GDC_LAUNCH() asm volatile("griddepcontrol.launch_dependents;")
#define GDC_WAIT()   asm volatile("griddepcontrol.wait;" ::: "memory")

__device__ __forceinline__ float warp_reduce(float s) {
#pragma unroll
    for (int o = 16; o; o >>= 1) s += __shfl_down_sync(0xFFFFFFFFu, s, o);
    return s;
}

__device__ __forceinline__ float dot4(float4 a, float4 b) {
    return a.x * b.x + a.y * b.y + a.z * b.z + a.w * b.w;
}

// Four consecutive streaming LDG.128 (stride 512 B) in one asm block.
__device__ __forceinline__ void ldg4x4(const float4* p,
                                       float4& a, float4& b, float4& c, float4& d) {
    asm volatile(
        "ld.global.cs.v4.f32 {%0,%1,%2,%3}, [%16];\n\t"
        "ld.global.cs.v4.f32 {%4,%5,%6,%7}, [%16+512];\n\t"
        "ld.global.cs.v4.f32 {%8,%9,%10,%11}, [%16+1024];\n\t"
        "ld.global.cs.v4.f32 {%12,%13,%14,%15}, [%16+1536];"
        : "=f"(a.x), "=f"(a.y), "=f"(a.z), "=f"(a.w),
          "=f"(b.x), "=f"(b.y), "=f"(b.z), "=f"(b.w),
          "=f"(c.x), "=f"(c.y), "=f"(c.z), "=f"(c.w),
          "=f"(d.x), "=f"(d.y), "=f"(d.z), "=f"(d.w)
        : "l"(p));
}

// TWO 1024-float rows dotted against the same vector; 16 LDG in flight.
__device__ __forceinline__ void row2_dot_1k(const float4* wA, const float4* wB,
                                            const float4* v4, int lane,
                                            float& outA, float& outB) {
    float4 a0,a1,a2,a3,a4,a5,a6,a7;
    float4 b0,b1,b2,b3,b4,b5,b6,b7;
    ldg4x4(wA + lane,       a0, a1, a2, a3);
    ldg4x4(wA + lane + 128, a4, a5, a6, a7);
    ldg4x4(wB + lane,       b0, b1, b2, b3);
    ldg4x4(wB + lane + 128, b4, b5, b6, b7);
    float sA = 0.f, sB = 0.f;
    float4 v;
    v = v4[lane];       sA += dot4(v, a0); sB += dot4(v, b0);
    v = v4[lane + 32];  sA += dot4(v, a1); sB += dot4(v, b1);
    v = v4[lane + 64];  sA += dot4(v, a2); sB += dot4(v, b2);
    v = v4[lane + 96];  sA += dot4(v, a3); sB += dot4(v, b3);
    v = v4[lane + 128]; sA += dot4(v, a4); sB += dot4(v, b4);
    v = v4[lane + 160]; sA += dot4(v, a5); sB += dot4(v, b5);
    v = v4[lane + 192]; sA += dot4(v, a6); sB += dot4(v, b6);
    v = v4[lane + 224]; sA += dot4(v, a7); sB += dot4(v, b7);
    outA += sA; outB += sB;
}

// ---------------------------------------------------------------------------
// K1: embedding gather + attention logits + softmax + context (one block)
// ---------------------------------------------------------------------------
__global__ void __launch_bounds__(512)
k_attn(const int* __restrict__ tok,
       const float* __restrict__ h0,
       const float* __restrict__ emb,
       const float* __restrict__ attn_w,
       const float* __restrict__ attn_b,
       const float* __restrict__ enc,
       float* __restrict__ out_attnw) {
    GDC_LAUNCH();     // release successors at entry
    __shared__ float s_ain[3 * HID];
    __shared__ float s_log[LEN];
    __shared__ float s_w[LEN];
    int t = threadIdx.x;            // 512 threads
    int token = tok[0];
    for (int i = t; i < HID; i += 512) {
        s_ain[i]           = emb[(size_t)token * HID + i];
        s_ain[HID + i]     = h0[i];
        s_ain[2 * HID + i] = h0[HID + i];
    }
    __syncthreads();

    int warp = t >> 5, lane = t & 31;   // 16 warps
    for (int l = warp; l < LEN; l += 16) {
        const float4* w = (const float4*)(attn_w + (size_t)l * 3 * HID);
        const float4* a = (const float4*)s_ain;
        float s = 0.f;
#pragma unroll
        for (int c = 0; c < 3; c++) {
            float4 w0, w1, w2, w3, w4, w5, w6, w7;
            const float4* base = w + lane + 256 * c;
            ldg4x4(base,       w0, w1, w2, w3);
            ldg4x4(base + 128, w4, w5, w6, w7);
            int i0 = lane + 256 * c;
            s += dot4(a[i0],       w0) + dot4(a[i0 + 32],  w1)
               + dot4(a[i0 + 64],  w2) + dot4(a[i0 + 96],  w3)
               + dot4(a[i0 + 128], w4) + dot4(a[i0 + 160], w5)
               + dot4(a[i0 + 192], w6) + dot4(a[i0 + 224], w7);
        }
        s = warp_reduce(s);
        if (lane == 0) s_log[l] = s + attn_b[l];
    }
    __syncthreads();

    if (t == 0) {
        float m = s_log[0];
        for (int l = 1; l < LEN; l++) m = fmaxf(m, s_log[l]);
        float sum = 0.f;
        for (int l = 0; l < LEN; l++) { float e = expf(s_log[l] - m); s_w[l] = e; sum += e; }
        float inv = 1.f / sum;
        for (int l = 0; l < LEN; l++) { s_w[l] *= inv; out_attnw[l] = s_w[l]; }
    }
    __syncthreads();

    for (int j = t; j < 2 * HID; j += 512) {
        float s = 0.f;
#pragma unroll
        for (int l = 0; l < LEN; l++) s += s_w[l] * enc[l * 2 * HID + j];
        g_concat[HID + j] = s;
    }
    for (int i = t; i < HID; i += 512) g_concat[i] = s_ain[i];
}

// ---------------------------------------------------------------------------
// K2: x = relu([emb;attn] @ comb_w.T + comb_b). Warp per ROW-PAIR.
// ---------------------------------------------------------------------------
__global__ void __launch_bounds__(128, 2)
k_comb(const float* __restrict__ comb_w,
       const float* __restrict__ comb_b) {
    GDC_LAUNCH();
    int t = threadIdx.x;
    int wid = t >> 5, lane = t & 31;
    int r0 = (blockIdx.x * 4 + wid) * 2;          // even row of pair
    const float4* wA = (const float4*)(comb_w + (size_t)r0 * 3 * HID);
    const float4* wB = (const float4*)(comb_w + (size_t)(r0 + 1) * 3 * HID);

    // prefetch chunk 0 (independent of parent)
    float4 a0,a1,a2,a3,a4,a5,a6,a7, b0,b1,b2,b3,b4,b5,b6,b7;
    ldg4x4(wA + lane,       a0, a1, a2, a3);
    ldg4x4(wA + lane + 128, a4, a5, a6, a7);
    ldg4x4(wB + lane,       b0, b1, b2, b3);
    ldg4x4(wB + lane + 128, b4, b5, b6, b7);
    GDC_WAIT();                                   // g_concat ready

    const float4* v = (const float4*)g_concat;
    float sA = 0.f, sB = 0.f;
    float4 vv;
    vv = v[lane];       sA += dot4(vv, a0); sB += dot4(vv, b0);
    vv = v[lane + 32];  sA += dot4(vv, a1); sB += dot4(vv, b1);
    vv = v[lane + 64];  sA += dot4(vv, a2); sB += dot4(vv, b2);
    vv = v[lane + 96];  sA += dot4(vv, a3); sB += dot4(vv, b3);
    vv = v[lane + 128]; sA += dot4(vv, a4); sB += dot4(vv, b4);
    vv = v[lane + 160]; sA += dot4(vv, a5); sB += dot4(vv, b5);
    vv = v[lane + 192]; sA += dot4(vv, a6); sB += dot4(vv, b6);
    vv = v[lane + 224]; sA += dot4(vv, a7); sB += dot4(vv, b7);
#pragma unroll
    for (int c = 1; c < 3; c++)
        row2_dot_1k(wA + 256 * c, wB + 256 * c, v + 256 * c, lane, sA, sB);
    sA = warp_reduce(sA);
    sB = warp_reduce(sB);
    if (lane == 0) {
        g_x[r0]     = fmaxf(sA + comb_b[r0], 0.f);
        g_x[r0 + 1] = fmaxf(sB + comb_b[r0 + 1], 0.f);
    }
}

// ---------------------------------------------------------------------------
// K3a: 256 blocks (ONE residency wave at 2/SM).
//  bids [0,128): layer-1 w_hh partials, 4 rows/warp (input-only, no wait)
//  bids [128,256): lstm layer-0, 8 units/block. Pre-wait = w_hh0 dots
//  (4 rows/warp); post-wait = w_ih0 dots (streams, x from L1).
// ---------------------------------------------------------------------------
__global__ void __launch_bounds__(256, 2)
k_lstm_a(const float* __restrict__ h0,
         const float* __restrict__ c0,
         const float* __restrict__ w_ih0,
         const float* __restrict__ w_hh0,
         const float* __restrict__ w_hh1,
         const float* __restrict__ b_ih0,
         const float* __restrict__ b_hh0,
         float* __restrict__ h_out,
         float* __restrict__ c_out) {
    GDC_LAUNCH();
    int bid = blockIdx.x;
    int t = threadIdx.x;
    int wid = t >> 5, lane = t & 31;

    if (bid < 128) {
        // ---- layer-1 w_hh partials: 4 rows/warp (2 x row2) ----
        int r0 = (bid * 8 + wid) * 4;
        const float4* h4 = (const float4*)(h0 + HID);
        float s0 = 0.f, s1 = 0.f, s2 = 0.f, s3 = 0.f;
        row2_dot_1k((const float4*)(w_hh1 + (size_t)r0 * HID),
                    (const float4*)(w_hh1 + (size_t)(r0 + 1) * HID),
                    h4, lane, s0, s1);
        row2_dot_1k((const float4*)(w_hh1 + (size_t)(r0 + 2) * HID),
                    (const float4*)(w_hh1 + (size_t)(r0 + 3) * HID),
                    h4, lane, s2, s3);
        s0 = warp_reduce(s0); s1 = warp_reduce(s1);
        s2 = warp_reduce(s2); s3 = warp_reduce(s3);
        if (lane == 0) {
            g_hh1[r0]     = s0; g_hh1[r0 + 1] = s1;
            g_hh1[r0 + 2] = s2; g_hh1[r0 + 3] = s3;
        }
        return;
    }

    // ---- lstm layer 0: 8 units/block ----
    __shared__ float s_g[4][8];                   // [gate][local unit]
    int b = bid - 128;
    int gate = wid & 3;
    int half = wid >> 2;                          // 0..1 -> units half*4..+3
    int u0 = b * 8 + half * 4;
    int r0 = gate * HID + u0;                     // 4 consecutive rows

    // pre-wait: w_hh0·h0 for 4 rows (inputs only)
    const float4* h4 = (const float4*)h0;
    float s0 = 0.f, s1 = 0.f, s2 = 0.f, s3 = 0.f;
    row2_dot_1k((const float4*)(w_hh0 + (size_t)r0 * HID),
                (const float4*)(w_hh0 + (size_t)(r0 + 1) * HID),
                h4, lane, s0, s1);
    row2_dot_1k((const float4*)(w_hh0 + (size_t)(r0 + 2) * HID),
                (const float4*)(w_hh0 + (size_t)(r0 + 3) * HID),
                h4, lane, s2, s3);
    GDC_WAIT();                                   // g_x ready

    // post-wait: w_ih0·x for the same 4 rows (x is L1-resident)
    const float4* x4 = (const float4*)g_x;
    row2_dot_1k((const float4*)(w_ih0 + (size_t)r0 * HID),
                (const float4*)(w_ih0 + (size_t)(r0 + 1) * HID),
                x4, lane, s0, s1);
    row2_dot_1k((const float4*)(w_ih0 + (size_t)(r0 + 2) * HID),
                (const float4*)(w_ih0 + (size_t)(r0 + 3) * HID),
                x4, lane, s2, s3);
    s0 = warp_reduce(s0); s1 = warp_reduce(s1);
    s2 = warp_reduce(s2); s3 = warp_reduce(s3);
    if (lane == 0) {
        s_g[gate][half * 4 + 0] = s0 + b_ih0[r0]     + b_hh0[r0];
        s_g[gate][half * 4 + 1] = s1 + b_ih0[r0 + 1] + b_hh0[r0 + 1];
        s_g[gate][half * 4 + 2] = s2 + b_ih0[r0 + 2] + b_hh0[r0 + 2];
        s_g[gate][half * 4 + 3] = s3 + b_ih0[r0 + 3] + b_hh0[r0 + 3];
    }
    __syncthreads();

    if (t < 8) {
        int u = b * 8 + t;
        float gi = s_g[0][t], gf = s_g[1][t], gg = s_g[2][t], go = s_g[3][t];
        float si = 1.f / (1.f + expf(-gi));
        float sf = 1.f / (1.f + expf(-gf));
        float so = 1.f / (1.f + expf(-go));
        float c2 = sf * c0[u] + si * tanhf(gg);
        float h2 = so * tanhf(c2);
        c_out[u] = c2;
        h_out[u] = h2;
        g_hl0[u] = h2;
    }
}

// ---------------------------------------------------------------------------
// K3b: lstm layer 1 — w_ih1 only (w_hh1 part precomputed into g_hh1).
// All 16 weight loads prefetched pre-wait; post-wait is L1 x-dots + gates.
// ---------------------------------------------------------------------------
__global__ void __launch_bounds__(256, 2)
k_lstm_b(const float* __restrict__ h0,
         const float* __restrict__ c0,
         const float* __restrict__ w_ih1,
         const float* __restrict__ b_ih1,
         const float* __restrict__ b_hh1,
         float* __restrict__ h_out,
         float* __restrict__ c_out) {
    GDC_LAUNCH();
    __shared__ float s_g[4][4];
    int t = threadIdx.x;
    int wid = t >> 5, lane = t & 31;
    int gate = wid & 3;
    int upair = wid >> 2;
    int u0 = blockIdx.x * 4 + upair * 2;
    int r0 = gate * HID + u0;

    const float4* wiA = (const float4*)(w_ih1 + (size_t)r0 * HID);
    const float4* wiB = (const float4*)(w_ih1 + (size_t)(r0 + 1) * HID);
    float4 a0,a1,a2,a3,a4,a5,a6,a7, b0,b1,b2,b3,b4,b5,b6,b7;
    ldg4x4(wiA + lane,       a0, a1, a2, a3);
    ldg4x4(wiA + lane + 128, a4, a5, a6, a7);
    ldg4x4(wiB + lane,       b0, b1, b2, b3);
    ldg4x4(wiB + lane + 128, b4, b5, b6, b7);
    GDC_WAIT();                                   // g_hl0 + g_hh1 ready

    const float4* x4 = (const float4*)g_hl0;
    float sA = 0.f, sB = 0.f;
    float4 v;
    v = x4[lane];       sA += dot4(v, a0); sB += dot4(v, b0);
    v = x4[lane + 32];  sA += dot4(v, a1); sB += dot4(v, b1);
    v = x4[lane + 64];  sA += dot4(v, a2); sB += dot4(v, b2);
    v = x4[lane + 96];  sA += dot4(v, a3); sB += dot4(v, b3);
    v = x4[lane + 128]; sA += dot4(v, a4); sB += dot4(v, b4);
    v = x4[lane + 160]; sA += dot4(v, a5); sB += dot4(v, b5);
    v = x4[lane + 192]; sA += dot4(v, a6); sB += dot4(v, b6);
    v = x4[lane + 224]; sA += dot4(v, a7); sB += dot4(v, b7);
    sA = warp_reduce(sA);
    sB = warp_reduce(sB);
    if (lane == 0) {
        s_g[gate][upair * 2]     = sA + g_hh1[r0]     + b_ih1[r0]     + b_hh1[r0];
        s_g[gate][upair * 2 + 1] = sB + g_hh1[r0 + 1] + b_ih1[r0 + 1] + b_hh1[r0 + 1];
    }
    __syncthreads();

    if (t < 4) {
        int u = blockIdx.x * 4 + t;
        float gi = s_g[0][t], gf = s_g[1][t], gg = s_g[2][t], go = s_g[3][t];
        float si = 1.f / (1.f + expf(-gi));
        float sf = 1.f / (1.f + expf(-gf));
        float so = 1.f / (1.f + expf(-go));
        float c2 = sf * c0[HID + u] + si * tanhf(gg);
        float h2 = so * tanhf(c2);
        c_out[u] = c2;
        h_out[u] = h2;
        g_hl1[u] = h2;
    }
}

// ---------------------------------------------------------------------------
// K5: logits (warp per ROW-PAIR) + per-block lse partials.
// ---------------------------------------------------------------------------
__global__ void __launch_bounds__(256, 2)
k_logits(const float* __restrict__ out_w,
         const float* __restrict__ out_b,
         float* __restrict__ logits) {
    GDC_LAUNCH();
    __shared__ float s_l[16];
    int t = threadIdx.x;
    int wid = t >> 5, lane = t & 31;
    int r0 = blockIdx.x * 16 + wid * 2;
    bool pair = (r0 + 1 < VOC);
    bool single = (!pair) && (r0 < VOC);

    float4 a0,a1,a2,a3,a4,a5,a6,a7, b0,b1,b2,b3,b4,b5,b6,b7;
    if (pair) {
        const float4* wA = (const float4*)(out_w + (size_t)r0 * HID);
        const float4* wB = (const float4*)(out_w + (size_t)(r0 + 1) * HID);
        ldg4x4(wA + lane,       a0, a1, a2, a3);
        ldg4x4(wA + lane + 128, a4, a5, a6, a7);
        ldg4x4(wB + lane,       b0, b1, b2, b3);
        ldg4x4(wB + lane + 128, b4, b5, b6, b7);
    } else if (single) {
        const float4* wA = (const float4*)(out_w + (size_t)r0 * HID);
        ldg4x4(wA + lane,       a0, a1, a2, a3);
        ldg4x4(wA + lane + 128, a4, a5, a6, a7);
    }
    GDC_WAIT();                                   // g_hl1 ready

    const float4* h4 = (const float4*)g_hl1;
    if (pair) {
        float sA = 0.f, sB = 0.f;
        float4 v;
        v = h4[lane];       sA += dot4(v, a0); sB += dot4(v, b0);
        v = h4[lane + 32];  sA += dot4(v, a1); sB += dot4(v, b1);
        v = h4[lane + 64];  sA += dot4(v, a2); sB += dot4(v, b2);
        v = h4[lane + 96];  sA += dot4(v, a3); sB += dot4(v, b3);
        v = h4[lane + 128]; sA += dot4(v, a4); sB += dot4(v, b4);
        v = h4[lane + 160]; sA += dot4(v, a5); sB += dot4(v, b5);
        v = h4[lane + 192]; sA += dot4(v, a6); sB += dot4(v, b6);
        v = h4[lane + 224]; sA += dot4(v, a7); sB += dot4(v, b7);
        sA = warp_reduce(sA);
        sB = warp_reduce(sB);
        if (lane == 0) {
            float lgA = sA + out_b[r0];
            float lgB = sB + out_b[r0 + 1];
            logits[r0] = lgA;
            logits[r0 + 1] = lgB;
            s_l[wid * 2] = lgA;
            s_l[wid * 2 + 1] = lgB;
        }
    } else if (single) {
        float s = dot4(h4[lane],       a0) + dot4(h4[lane + 32],  a1)
                + dot4(h4[lane + 64],  a2) + dot4(h4[lane + 96],  a3)
                + dot4(h4[lane + 128], a4) + dot4(h4[lane + 160], a5)
                + dot4(h4[lane + 192], a6) + dot4(h4[lane + 224], a7);
        s = warp_reduce(s);
        if (lane == 0) {
            float lg = s + out_b[r0];
            logits[r0] = lg;
            s_l[wid * 2] = lg;
            s_l[wid * 2 + 1] = -INFINITY;
        }
    } else if (lane == 0) {
        s_l[wid * 2] = -INFINITY;
        s_l[wid * 2 + 1] = -INFINITY;
    }
    __syncthreads();

    if (t == 0) {
        float m = s_l[0];
#pragma unroll
        for (int k = 1; k < 16; k++) m = fmaxf(m, s_l[k]);
        float sum = 0.f;
#pragma unroll
        for (int k = 0; k < 16; k++) sum += expf(s_l[k] - m);
        g_pm[blockIdx.x] = m;
        g_ps[blockIdx.x] = sum;
    }
}

// ---------------------------------------------------------------------------
// K6: fused log-sum-exp + subtract.
// ---------------------------------------------------------------------------
__global__ void __launch_bounds__(256)
k_finish(float* __restrict__ logits) {
    GDC_WAIT();
    __shared__ float red[256];
    int t = threadIdx.x;
    float m = -INFINITY;
    for (int i = t; i < NPART; i += 256) m = fmaxf(m, g_pm[i]);
    red[t] = m;
    __syncthreads();
#pragma unroll
    for (int o = 128; o; o >>= 1) {
        if (t < o) red[t] = fmaxf(red[t], red[t + o]);
        __syncthreads();
    }
    m = red[0];
    __syncthreads();
    float s = 0.f;
    for (int i = t; i < NPART; i += 256) s += g_ps[i] * expf(g_pm[i] - m);
    red[t] = s;
    __syncthreads();
#pragma unroll
    for (int o = 128; o; o >>= 1) {
        if (t < o) red[t] += red[t + o];
        __syncthreads();
    }
    __syncthreads();
    float lse = m + logf(red[0]);

    int idx = blockIdx.x * 256 + t;
    if (idx < VOC) logits[idx] -= lse;
}

// ---------------------------------------------------------------------------
// host: PDL launch helper
// ---------------------------------------------------------------------------
static void launch_pdl(const void* fn, dim3 grid, dim3 block, void** args) {
    cudaLaunchConfig_t cfg = {};
    cfg.gridDim = grid;
    cfg.blockDim = block;
    cfg.dynamicSmemBytes = 0;
    cfg.stream = 0;
    cudaLaunchAttribute at[1];
    at[0].id = cudaLaunchAttributeProgrammaticStreamSerialization;
    at[0].val.programmaticStreamSerializationAllowed = 1;
    cfg.attrs = at;
    cfg.numAttrs = 1;
    cudaLaunchKernelExC(&cfg, fn, args);
}

// ---------------------------------------------------------------------------
// Output layout: [log_probs(V) | h_new(2*H) | c_new(2*H) | attn_weights(L)]
// ---------------------------------------------------------------------------
extern "C" void kernel_launch(void* const* d_in, const int* in_sizes, int n_in,
                              void* d_out, int out_size) {
    const int*   tok    = (const int*)  d_in[0];
    const float* h0     = (const float*)d_in[1];
    const float* c0     = (const float*)d_in[2];
    const float* enc    = (const float*)d_in[3];
    const float* emb    = (const float*)d_in[4];
    const float* attn_w = (const float*)d_in[5];
    const float* attn_b = (const float*)d_in[6];
    const float* comb_w = (const float*)d_in[7];
    const float* comb_b = (const float*)d_in[8];
    const float* w_ih0  = (const float*)d_in[9];
    const float* w_hh0  = (const float*)d_in[10];
    const float* b_ih0  = (const float*)d_in[11];
    const float* b_hh0  = (const float*)d_in[12];
    const float* w_ih1  = (const float*)d_in[13];
    const float* w_hh1  = (const float*)d_in[14];
    const float* b_ih1  = (const float*)d_in[15];
    const float* b_hh1  = (const float*)d_in[16];
    const float* out_w  = (const float*)d_in[17];
    const float* out_b  = (const float*)d_in[18];

    float* out      = (float*)d_out;
    float* o_logp   = out;
    float* o_h      = out + VOC;
    float* o_c      = out + VOC + 2 * HID;
    float* o_attn   = out + VOC + 4 * HID;

    k_attn<<<1, 512>>>(tok, h0, emb, attn_w, attn_b, enc, o_attn);

    {
        void* args[] = {(void*)&comb_w, (void*)&comb_b};
        launch_pdl((const void*)k_comb, dim3(128), dim3(128), args);
    }
    {
        float* ho = o_h;
        float* co = o_c;
        void* args[] = {(void*)&h0, (void*)&c0, (void*)&w_ih0, (void*)&w_hh0,
                        (void*)&w_hh1, (void*)&b_ih0, (void*)&b_hh0, &ho, &co};
        launch_pdl((const void*)k_lstm_a, dim3(256), dim3(256), args);
    }
    {
        float* ho = o_h + HID;
        float* co = o_c + HID;
        void* args[] = {(void*)&h0, (void*)&c0, (void*)&w_ih1,
                        (void*)&b_ih1, (void*)&b_hh1, &ho, &co};
        launch_pdl((const void*)k_lstm_b, dim3(256), dim3(256), args);
    }
    {
        void* args[] = {(void*)&out_w, (void*)&out_b, (void*)&o_logp};
        launch_pdl((const void*)k_logits, dim3(NPART), dim3(256), args);
    }
    {
        void* args[] = {(void*)&o_logp};
        launch_pdl((const void*)k_finish, dim3((VOC + 255) / 256), dim3(256), args);
    }
}

// round 17
// speedup vs baseline: 1.1872x; 1.0567x over previous
#include <cuda_runtime.h>
#include <math.h>

#define HID 1024
#define LEN 40
#define VOC 50257
#define NPART 3142   // ceil(VOC/16) logits blocks

// ---- scratch (no allocations allowed) ----
__device__ float g_alog[LEN];         // attention logits
__device__ float g_concat[3 * HID];   // [embedded ; attn_applied]
__device__ float g_x[HID];            // relu(comb) output
__device__ float g_hl0[HID];          // layer-0 hidden out
__device__ float g_hl1[HID];          // layer-1 hidden out
__device__ float g_hh1[4 * HID];      // w_hh1·h0[1] partials (layer 1)
__device__ float g_pm[NPART];         // per-block logit max
__device__ float g_ps[NPART];         // per-block expsum

#define GDC_LAUNCH() asm volatile("griddepcontrol.launch_dependents;")
#define GDC_WAIT()   asm volatile("griddepcontrol.wait;" ::: "memory")

__device__ __forceinline__ float warp_reduce(float s) {
#pragma unroll
    for (int o = 16; o; o >>= 1) s += __shfl_down_sync(0xFFFFFFFFu, s, o);
    return s;
}

__device__ __forceinline__ float dot4(float4 a, float4 b) {
    return a.x * b.x + a.y * b.y + a.z * b.z + a.w * b.w;
}

// Four consecutive streaming LDG.128 (stride 512 B) in one asm block.
__device__ __forceinline__ void ldg4x4(const float4* p,
                                       float4& a, float4& b, float4& c, float4& d) {
    asm volatile(
        "ld.global.cs.v4.f32 {%0,%1,%2,%3}, [%16];\n\t"
        "ld.global.cs.v4.f32 {%4,%5,%6,%7}, [%16+512];\n\t"
        "ld.global.cs.v4.f32 {%8,%9,%10,%11}, [%16+1024];\n\t"
        "ld.global.cs.v4.f32 {%12,%13,%14,%15}, [%16+1536];"
        : "=f"(a.x), "=f"(a.y), "=f"(a.z), "=f"(a.w),
          "=f"(b.x), "=f"(b.y), "=f"(b.z), "=f"(b.w),
          "=f"(c.x), "=f"(c.y), "=f"(c.z), "=f"(c.w),
          "=f"(d.x), "=f"(d.y), "=f"(d.z), "=f"(d.w)
        : "l"(p));
}

// TWO 1024-float rows dotted against the same vector; 16 LDG in flight.
__device__ __forceinline__ void row2_dot_1k(const float4* wA, const float4* wB,
                                            const float4* v4, int lane,
                                            float& outA, float& outB) {
    float4 a0,a1,a2,a3,a4,a5,a6,a7;
    float4 b0,b1,b2,b3,b4,b5,b6,b7;
    ldg4x4(wA + lane,       a0, a1, a2, a3);
    ldg4x4(wA + lane + 128, a4, a5, a6, a7);
    ldg4x4(wB + lane,       b0, b1, b2, b3);
    ldg4x4(wB + lane + 128, b4, b5, b6, b7);
    float sA = 0.f, sB = 0.f;
    float4 v;
    v = v4[lane];       sA += dot4(v, a0); sB += dot4(v, b0);
    v = v4[lane + 32];  sA += dot4(v, a1); sB += dot4(v, b1);
    v = v4[lane + 64];  sA += dot4(v, a2); sB += dot4(v, b2);
    v = v4[lane + 96];  sA += dot4(v, a3); sB += dot4(v, b3);
    v = v4[lane + 128]; sA += dot4(v, a4); sB += dot4(v, b4);
    v = v4[lane + 160]; sA += dot4(v, a5); sB += dot4(v, b5);
    v = v4[lane + 192]; sA += dot4(v, a6); sB += dot4(v, b6);
    v = v4[lane + 224]; sA += dot4(v, a7); sB += dot4(v, b7);
    outA += sA; outB += sB;
}

// ---------------------------------------------------------------------------
// K0: attention logits — block l computes logit l (INPUT-ONLY, 40 blocks)
// ---------------------------------------------------------------------------
__global__ void __launch_bounds__(256)
k_attn_log(const int* __restrict__ tok,
           const float* __restrict__ h0,
           const float* __restrict__ emb,
           const float* __restrict__ attn_w,
           const float* __restrict__ attn_b) {
    GDC_LAUNCH();
    __shared__ float s_part[8];
    int t = threadIdx.x;
    int wid = t >> 5, lane = t & 31;
    int l = blockIdx.x;
    int token = tok[0];

    const float4* w  = (const float4*)(attn_w + (size_t)l * 3 * HID);
    const float4* e4 = (const float4*)(emb + (size_t)token * HID);
    const float4* h4 = (const float4*)h0;   // 2*HID flattened

    float s = 0.f;
#pragma unroll
    for (int k = 0; k < 3; k++) {           // 768 float4 over 256 threads
        int i = t + 256 * k;
        float4 wv = __ldcs(&w[i]);
        float4 vv = (i < 256) ? e4[i] : h4[i - 256];
        s += dot4(vv, wv);
    }
    s = warp_reduce(s);
    if (lane == 0) s_part[wid] = s;
    __syncthreads();
    if (t == 0) {
        float tot = 0.f;
#pragma unroll
        for (int k = 0; k < 8; k++) tot += s_part[k];
        g_alog[l] = tot + attn_b[l];
    }
}

// ---------------------------------------------------------------------------
// K1: softmax + context + concat assembly (one block)
// ---------------------------------------------------------------------------
__global__ void __launch_bounds__(512)
k_attn_ctx(const int* __restrict__ tok,
           const float* __restrict__ h0,
           const float* __restrict__ emb,
           const float* __restrict__ enc,
           float* __restrict__ out_attnw) {
    GDC_LAUNCH();
    __shared__ float s_w[LEN];
    int t = threadIdx.x;
    int token = tok[0];
    GDC_WAIT();                               // g_alog ready

    if (t == 0) {
        float m = g_alog[0];
        for (int l = 1; l < LEN; l++) m = fmaxf(m, g_alog[l]);
        float sum = 0.f;
        for (int l = 0; l < LEN; l++) { float e = expf(g_alog[l] - m); s_w[l] = e; sum += e; }
        float inv = 1.f / sum;
        for (int l = 0; l < LEN; l++) { s_w[l] *= inv; out_attnw[l] = s_w[l]; }
    }
    __syncthreads();

    // context: attn_applied[j] = sum_l w[l] * enc[l, j]
    for (int j = t; j < 2 * HID; j += 512) {
        float s = 0.f;
#pragma unroll
        for (int l = 0; l < LEN; l++) s += s_w[l] * enc[l * 2 * HID + j];
        g_concat[HID + j] = s;
    }
    // embedded part
    for (int i = t; i < HID; i += 512)
        g_concat[i] = emb[(size_t)token * HID + i];
}

// ---------------------------------------------------------------------------
// K2: x = relu([emb;attn] @ comb_w.T + comb_b). Warp per ROW-PAIR.
// ---------------------------------------------------------------------------
__global__ void __launch_bounds__(128, 2)
k_comb(const float* __restrict__ comb_w,
       const float* __restrict__ comb_b) {
    GDC_LAUNCH();
    int t = threadIdx.x;
    int wid = t >> 5, lane = t & 31;
    int r0 = (blockIdx.x * 4 + wid) * 2;          // even row of pair
    const float4* wA = (const float4*)(comb_w + (size_t)r0 * 3 * HID);
    const float4* wB = (const float4*)(comb_w + (size_t)(r0 + 1) * 3 * HID);

    // prefetch chunk 0 (independent of parent)
    float4 a0,a1,a2,a3,a4,a5,a6,a7, b0,b1,b2,b3,b4,b5,b6,b7;
    ldg4x4(wA + lane,       a0, a1, a2, a3);
    ldg4x4(wA + lane + 128, a4, a5, a6, a7);
    ldg4x4(wB + lane,       b0, b1, b2, b3);
    ldg4x4(wB + lane + 128, b4, b5, b6, b7);
    GDC_WAIT();                                   // g_concat ready

    const float4* v = (const float4*)g_concat;
    float sA = 0.f, sB = 0.f;
    float4 vv;
    vv = v[lane];       sA += dot4(vv, a0); sB += dot4(vv, b0);
    vv = v[lane + 32];  sA += dot4(vv, a1); sB += dot4(vv, b1);
    vv = v[lane + 64];  sA += dot4(vv, a2); sB += dot4(vv, b2);
    vv = v[lane + 96];  sA += dot4(vv, a3); sB += dot4(vv, b3);
    vv = v[lane + 128]; sA += dot4(vv, a4); sB += dot4(vv, b4);
    vv = v[lane + 160]; sA += dot4(vv, a5); sB += dot4(vv, b5);
    vv = v[lane + 192]; sA += dot4(vv, a6); sB += dot4(vv, b6);
    vv = v[lane + 224]; sA += dot4(vv, a7); sB += dot4(vv, b7);
#pragma unroll
    for (int c = 1; c < 3; c++)
        row2_dot_1k(wA + 256 * c, wB + 256 * c, v + 256 * c, lane, sA, sB);
    sA = warp_reduce(sA);
    sB = warp_reduce(sB);
    if (lane == 0) {
        g_x[r0]     = fmaxf(sA + comb_b[r0], 0.f);
        g_x[r0 + 1] = fmaxf(sB + comb_b[r0 + 1], 0.f);
    }
}

// ---------------------------------------------------------------------------
// K3a: blocks [0,256): layer-1 w_hh partials (INPUT-ONLY, no wait).
//      blocks [256,512): full lstm layer-0 cell with PDL.
// ---------------------------------------------------------------------------
__global__ void __launch_bounds__(256, 2)
k_lstm_a(const float* __restrict__ h0,
         const float* __restrict__ c0,
         const float* __restrict__ w_ih0,
         const float* __restrict__ w_hh0,
         const float* __restrict__ w_hh1,
         const float* __restrict__ b_ih0,
         const float* __restrict__ b_hh0,
         float* __restrict__ h_out,
         float* __restrict__ c_out) {
    GDC_LAUNCH();
    int bid = blockIdx.x;
    int t = threadIdx.x;
    int wid = t >> 5, lane = t & 31;

    if (bid < 256) {
        // ---- layer-1 w_hh partials: 4096 rows, 2 rows/warp ----
        int r0 = (bid * 8 + wid) * 2;
        const float4* wA = (const float4*)(w_hh1 + (size_t)r0 * HID);
        const float4* wB = (const float4*)(w_hh1 + (size_t)(r0 + 1) * HID);
        const float4* h4 = (const float4*)(h0 + HID);
        float sA = 0.f, sB = 0.f;
        row2_dot_1k(wA, wB, h4, lane, sA, sB);
        sA = warp_reduce(sA);
        sB = warp_reduce(sB);
        if (lane == 0) { g_hh1[r0] = sA; g_hh1[r0 + 1] = sB; }
        return;
    }

    // ---- lstm layer 0: 4 units/block ----
    __shared__ float s_g[4][4];
    int gate = wid & 3;
    int upair = wid >> 2;
    int u0 = (bid - 256) * 4 + upair * 2;
    int r0 = gate * HID + u0;

    // pre-wait: w_hh0·h0 (inputs only) + w_ih0 prefetch
    const float4* whA = (const float4*)(w_hh0 + (size_t)r0 * HID);
    const float4* whB = (const float4*)(w_hh0 + (size_t)(r0 + 1) * HID);
    const float4* h4  = (const float4*)h0;
    float sA = 0.f, sB = 0.f;
    row2_dot_1k(whA, whB, h4, lane, sA, sB);

    const float4* wiA = (const float4*)(w_ih0 + (size_t)r0 * HID);
    const float4* wiB = (const float4*)(w_ih0 + (size_t)(r0 + 1) * HID);
    float4 a0,a1,a2,a3,a4,a5,a6,a7, b0,b1,b2,b3,b4,b5,b6,b7;
    ldg4x4(wiA + lane,       a0, a1, a2, a3);
    ldg4x4(wiA + lane + 128, a4, a5, a6, a7);
    ldg4x4(wiB + lane,       b0, b1, b2, b3);
    ldg4x4(wiB + lane + 128, b4, b5, b6, b7);
    GDC_WAIT();                                   // g_x ready

    const float4* x4 = (const float4*)g_x;
    float4 v;
    v = x4[lane];       sA += dot4(v, a0); sB += dot4(v, b0);
    v = x4[lane + 32];  sA += dot4(v, a1); sB += dot4(v, b1);
    v = x4[lane + 64];  sA += dot4(v, a2); sB += dot4(v, b2);
    v = x4[lane + 96];  sA += dot4(v, a3); sB += dot4(v, b3);
    v = x4[lane + 128]; sA += dot4(v, a4); sB += dot4(v, b4);
    v = x4[lane + 160]; sA += dot4(v, a5); sB += dot4(v, b5);
    v = x4[lane + 192]; sA += dot4(v, a6); sB += dot4(v, b6);
    v = x4[lane + 224]; sA += dot4(v, a7); sB += dot4(v, b7);
    sA = warp_reduce(sA);
    sB = warp_reduce(sB);
    if (lane == 0) {
        s_g[gate][upair * 2]     = sA + b_ih0[r0]     + b_hh0[r0];
        s_g[gate][upair * 2 + 1] = sB + b_ih0[r0 + 1] + b_hh0[r0 + 1];
    }
    __syncthreads();

    if (t < 4) {
        int u = (bid - 256) * 4 + t;
        float gi = s_g[0][t], gf = s_g[1][t], gg = s_g[2][t], go = s_g[3][t];
        float si = 1.f / (1.f + expf(-gi));
        float sf = 1.f / (1.f + expf(-gf));
        float so = 1.f / (1.f + expf(-go));
        float c2 = sf * c0[u] + si * tanhf(gg);
        float h2 = so * tanhf(c2);
        c_out[u] = c2;
        h_out[u] = h2;
        g_hl0[u] = h2;
    }
}

// ---------------------------------------------------------------------------
// K3b: lstm layer 1 — w_ih1 only (w_hh1 part precomputed into g_hh1).
// ---------------------------------------------------------------------------
__global__ void __launch_bounds__(256, 2)
k_lstm_b(const float* __restrict__ h0,
         const float* __restrict__ c0,
         const float* __restrict__ w_ih1,
         const float* __restrict__ b_ih1,
         const float* __restrict__ b_hh1,
         float* __restrict__ h_out,
         float* __restrict__ c_out) {
    GDC_LAUNCH();
    __shared__ float s_g[4][4];
    int t = threadIdx.x;
    int wid = t >> 5, lane = t & 31;
    int gate = wid & 3;
    int upair = wid >> 2;
    int u0 = blockIdx.x * 4 + upair * 2;
    int r0 = gate * HID + u0;

    const float4* wiA = (const float4*)(w_ih1 + (size_t)r0 * HID);
    const float4* wiB = (const float4*)(w_ih1 + (size_t)(r0 + 1) * HID);
    float4 a0,a1,a2,a3,a4,a5,a6,a7, b0,b1,b2,b3,b4,b5,b6,b7;
    ldg4x4(wiA + lane,       a0, a1, a2, a3);
    ldg4x4(wiA + lane + 128, a4, a5, a6, a7);
    ldg4x4(wiB + lane,       b0, b1, b2, b3);
    ldg4x4(wiB + lane + 128, b4, b5, b6, b7);
    GDC_WAIT();                                   // g_hl0 + g_hh1 ready

    const float4* x4 = (const float4*)g_hl0;
    float sA = 0.f, sB = 0.f;
    float4 v;
    v = x4[lane];       sA += dot4(v, a0); sB += dot4(v, b0);
    v = x4[lane + 32];  sA += dot4(v, a1); sB += dot4(v, b1);
    v = x4[lane + 64];  sA += dot4(v, a2); sB += dot4(v, b2);
    v = x4[lane + 96];  sA += dot4(v, a3); sB += dot4(v, b3);
    v = x4[lane + 128]; sA += dot4(v, a4); sB += dot4(v, b4);
    v = x4[lane + 160]; sA += dot4(v, a5); sB += dot4(v, b5);
    v = x4[lane + 192]; sA += dot4(v, a6); sB += dot4(v, b6);
    v = x4[lane + 224]; sA += dot4(v, a7); sB += dot4(v, b7);
    sA = warp_reduce(sA);
    sB = warp_reduce(sB);
    if (lane == 0) {
        s_g[gate][upair * 2]     = sA + g_hh1[r0]     + b_ih1[r0]     + b_hh1[r0];
        s_g[gate][upair * 2 + 1] = sB + g_hh1[r0 + 1] + b_ih1[r0 + 1] + b_hh1[r0 + 1];
    }
    __syncthreads();

    if (t < 4) {
        int u = blockIdx.x * 4 + t;
        float gi = s_g[0][t], gf = s_g[1][t], gg = s_g[2][t], go = s_g[3][t];
        float si = 1.f / (1.f + expf(-gi));
        float sf = 1.f / (1.f + expf(-gf));
        float so = 1.f / (1.f + expf(-go));
        float c2 = sf * c0[HID + u] + si * tanhf(gg);
        float h2 = so * tanhf(c2);
        c_out[u] = c2;
        h_out[u] = h2;
        g_hl1[u] = h2;
    }
}

// ---------------------------------------------------------------------------
// K5: logits (warp per ROW-PAIR) + per-block lse partials.
// ---------------------------------------------------------------------------
__global__ void __launch_bounds__(256, 2)
k_logits(const float* __restrict__ out_w,
         const float* __restrict__ out_b,
         float* __restrict__ logits) {
    GDC_LAUNCH();
    __shared__ float s_l[16];
    int t = threadIdx.x;
    int wid = t >> 5, lane = t & 31;
    int r0 = blockIdx.x * 16 + wid * 2;
    bool pair = (r0 + 1 < VOC);
    bool single = (!pair) && (r0 < VOC);

    float4 a0,a1,a2,a3,a4,a5,a6,a7, b0,b1,b2,b3,b4,b5,b6,b7;
    if (pair) {
        const float4* wA = (const float4*)(out_w + (size_t)r0 * HID);
        const float4* wB = (const float4*)(out_w + (size_t)(r0 + 1) * HID);
        ldg4x4(wA + lane,       a0, a1, a2, a3);
        ldg4x4(wA + lane + 128, a4, a5, a6, a7);
        ldg4x4(wB + lane,       b0, b1, b2, b3);
        ldg4x4(wB + lane + 128, b4, b5, b6, b7);
    } else if (single) {
        const float4* wA = (const float4*)(out_w + (size_t)r0 * HID);
        ldg4x4(wA + lane,       a0, a1, a2, a3);
        ldg4x4(wA + lane + 128, a4, a5, a6, a7);
    }
    GDC_WAIT();                                   // g_hl1 ready

    const float4* h4 = (const float4*)g_hl1;
    if (pair) {
        float sA = 0.f, sB = 0.f;
        float4 v;
        v = h4[lane];       sA += dot4(v, a0); sB += dot4(v, b0);
        v = h4[lane + 32];  sA += dot4(v, a1); sB += dot4(v, b1);
        v = h4[lane + 64];  sA += dot4(v, a2); sB += dot4(v, b2);
        v = h4[lane + 96];  sA += dot4(v, a3); sB += dot4(v, b3);
        v = h4[lane + 128]; sA += dot4(v, a4); sB += dot4(v, b4);
        v = h4[lane + 160]; sA += dot4(v, a5); sB += dot4(v, b5);
        v = h4[lane + 192]; sA += dot4(v, a6); sB += dot4(v, b6);
        v = h4[lane + 224]; sA += dot4(v, a7); sB += dot4(v, b7);
        sA = warp_reduce(sA);
        sB = warp_reduce(sB);
        if (lane == 0) {
            float lgA = sA + out_b[r0];
            float lgB = sB + out_b[r0 + 1];
            logits[r0] = lgA;
            logits[r0 + 1] = lgB;
            s_l[wid * 2] = lgA;
            s_l[wid * 2 + 1] = lgB;
        }
    } else if (single) {
        float s = dot4(h4[lane],       a0) + dot4(h4[lane + 32],  a1)
                + dot4(h4[lane + 64],  a2) + dot4(h4[lane + 96],  a3)
                + dot4(h4[lane + 128], a4) + dot4(h4[lane + 160], a5)
                + dot4(h4[lane + 192], a6) + dot4(h4[lane + 224], a7);
        s = warp_reduce(s);
        if (lane == 0) {
            float lg = s + out_b[r0];
            logits[r0] = lg;
            s_l[wid * 2] = lg;
            s_l[wid * 2 + 1] = -INFINITY;
        }
    } else if (lane == 0) {
        s_l[wid * 2] = -INFINITY;
        s_l[wid * 2 + 1] = -INFINITY;
    }
    __syncthreads();

    if (t == 0) {
        float m = s_l[0];
#pragma unroll
        for (int k = 1; k < 16; k++) m = fmaxf(m, s_l[k]);
        float sum = 0.f;
#pragma unroll
        for (int k = 0; k < 16; k++) sum += expf(s_l[k] - m);
        g_pm[blockIdx.x] = m;
        g_ps[blockIdx.x] = sum;
    }
}

// ---------------------------------------------------------------------------
// K6: fused log-sum-exp + subtract.
// ---------------------------------------------------------------------------
__global__ void __launch_bounds__(256)
k_finish(float* __restrict__ logits) {
    GDC_WAIT();
    __shared__ float red[256];
    int t = threadIdx.x;
    float m = -INFINITY;
    for (int i = t; i < NPART; i += 256) m = fmaxf(m, g_pm[i]);
    red[t] = m;
    __syncthreads();
#pragma unroll
    for (int o = 128; o; o >>= 1) {
        if (t < o) red[t] = fmaxf(red[t], red[t + o]);
        __syncthreads();
    }
    m = red[0];
    __syncthreads();
    float s = 0.f;
    for (int i = t; i < NPART; i += 256) s += g_ps[i] * expf(g_pm[i] - m);
    red[t] = s;
    __syncthreads();
#pragma unroll
    for (int o = 128; o; o >>= 1) {
        if (t < o) red[t] += red[t + o];
        __syncthreads();
    }
    __syncthreads();
    float lse = m + logf(red[0]);

    int idx = blockIdx.x * 256 + t;
    if (idx < VOC) logits[idx] -= lse;
}

// ---------------------------------------------------------------------------
// host: PDL launch helper
// ---------------------------------------------------------------------------
static void launch_pdl(const void* fn, dim3 grid, dim3 block, void** args) {
    cudaLaunchConfig_t cfg = {};
    cfg.gridDim = grid;
    cfg.blockDim = block;
    cfg.dynamicSmemBytes = 0;
    cfg.stream = 0;
    cudaLaunchAttribute at[1];
    at[0].id = cudaLaunchAttributeProgrammaticStreamSerialization;
    at[0].val.programmaticStreamSerializationAllowed = 1;
    cfg.attrs = at;
    cfg.numAttrs = 1;
    cudaLaunchKernelExC(&cfg, fn, args);
}

// ---------------------------------------------------------------------------
// Output layout: [log_probs(V) | h_new(2*H) | c_new(2*H) | attn_weights(L)]
// ---------------------------------------------------------------------------
extern "C" void kernel_launch(void* const* d_in, const int* in_sizes, int n_in,
                              void* d_out, int out_size) {
    const int*   tok    = (const int*)  d_in[0];
    const float* h0     = (const float*)d_in[1];
    const float* c0     = (const float*)d_in[2];
    const float* enc    = (const float*)d_in[3];
    const float* emb    = (const float*)d_in[4];
    const float* attn_w = (const float*)d_in[5];
    const float* attn_b = (const float*)d_in[6];
    const float* comb_w = (const float*)d_in[7];
    const float* comb_b = (const float*)d_in[8];
    const float* w_ih0  = (const float*)d_in[9];
    const float* w_hh0  = (const float*)d_in[10];
    const float* b_ih0  = (const float*)d_in[11];
    const float* b_hh0  = (const float*)d_in[12];
    const float* w_ih1  = (const float*)d_in[13];
    const float* w_hh1  = (const float*)d_in[14];
    const float* b_ih1  = (const float*)d_in[15];
    const float* b_hh1  = (const float*)d_in[16];
    const float* out_w  = (const float*)d_in[17];
    const float* out_b  = (const float*)d_in[18];

    float* out      = (float*)d_out;
    float* o_logp   = out;
    float* o_h      = out + VOC;
    float* o_c      = out + VOC + 2 * HID;
    float* o_attn   = out + VOC + 4 * HID;

    k_attn_log<<<LEN, 256>>>(tok, h0, emb, attn_w, attn_b);

    {
        void* args[] = {(void*)&tok, (void*)&h0, (void*)&emb, (void*)&enc,
                        (void*)&o_attn};
        launch_pdl((const void*)k_attn_ctx, dim3(1), dim3(512), args);
    }
    {
        void* args[] = {(void*)&comb_w, (void*)&comb_b};
        launch_pdl((const void*)k_comb, dim3(128), dim3(128), args);
    }
    {
        float* ho = o_h;
        float* co = o_c;
        void* args[] = {(void*)&h0, (void*)&c0, (void*)&w_ih0, (void*)&w_hh0,
                        (void*)&w_hh1, (void*)&b_ih0, (void*)&b_hh0, &ho, &co};
        launch_pdl((const void*)k_lstm_a, dim3(512), dim3(256), args);
    }
    {
        float* ho = o_h + HID;
        float* co = o_c + HID;
        void* args[] = {(void*)&h0, (void*)&c0, (void*)&w_ih1,
                        (void*)&b_ih1, (void*)&b_hh1, &ho, &co};
        launch_pdl((const void*)k_lstm_b, dim3(256), dim3(256), args);
    }
    {
        void* args[] = {(void*)&out_w, (void*)&out_b, (void*)&o_logp};
        launch_pdl((const void*)k_logits, dim3(NPART), dim3(256), args);
    }
    {
        void* args[] = {(void*)&o_logp};
        launch_pdl((const void*)k_finish, dim3((VOC + 255) / 256), dim3(256), args);
    }
}